// round 10
// baseline (speedup 1.0000x reference)
#include <cuda_runtime.h>
#include <cuda_bf16.h>
#include <math.h>
#include <stdint.h>

// Problem constants
#define BATCH 2
#define SEQL  2048
#define HD    768
#define ED    1536
#define ND    16
#define RD    4
#define NLAYERS 8
#define TOK   (BATCH*SEQL)     // 4096 tokens
#define DBCW  36               // R + 2N

// weight scratch offsets (elements)
#define IN_WOFF   0
#define OUT_WOFF  (HD*2*ED)
#define FRAC_WOFF (OUT_WOFF + ED*HD)
#define WT_TOTAL  (FRAC_WOFF + 3*HD*HD)

// ---------------- scratch (static device globals; no allocation) -------------
__device__ float g_hs  [TOK*HD];
__device__ float g_proj[TOK*2*ED];
__device__ float g_u   [TOK*ED];
__device__ float g_dbc [TOK*DBCW];
__device__ float g_dt  [TOK*ED];
__device__ float g_t3  [3*TOK*HD];

__device__ __align__(16) uint16_t g_wh [WT_TOTAL];
__device__ __align__(16) uint16_t g_wl [WT_TOTAL];
__device__ __align__(16) uint16_t g_xh [TOK*HD];
__device__ __align__(16) uint16_t g_xl [TOK*HD];
__device__ __align__(16) uint16_t g_yh [TOK*ED];
__device__ __align__(16) uint16_t g_yl [TOK*ED];
__device__ __align__(16) uint16_t g_hsh[TOK*HD];
__device__ __align__(16) uint16_t g_hsl[TOK*HD];
__device__ __align__(16) uint16_t g_t1h[3*TOK*HD];
__device__ __align__(16) uint16_t g_t1l[3*TOK*HD];
__device__ __align__(16) uint16_t g_t2h[3*TOK*HD];
__device__ __align__(16) uint16_t g_t2l[3*TOK*HD];

// ---------------- math helpers ----------------
__device__ __forceinline__ float sigmoidf_(float x) {
    return 1.0f / (1.0f + __expf(-x));
}
__device__ __forceinline__ float siluf_(float x) {
    return x / (1.0f + __expf(-x));
}
__device__ __forceinline__ float softplusf_(float x) {
    if (x > 20.0f) return x;
    return __logf(1.0f + __expf(x));
}
__device__ __forceinline__ float ex2a(float x) {
    float r; asm("ex2.approx.ftz.f32 %0, %1;" : "=f"(r) : "f"(x)); return r;
}
__device__ __forceinline__ void split_bf(float v, uint16_t& h, uint16_t& l) {
    uint32_t b = __float_as_uint(v);
    h = (uint16_t)(b >> 16);
    float hf = __uint_as_float(b & 0xFFFF0000u);
    l = (uint16_t)(__float_as_uint(v - hf) >> 16);
}

__device__ __forceinline__ uint32_t smem_u32(const void* p) {
    uint32_t a;
    asm("{ .reg .u64 t; cvta.to.shared.u64 t, %1; cvt.u32.u64 %0, t; }"
        : "=r"(a) : "l"(p));
    return a;
}

// SW128 swizzle on 128-byte rows (16B granularity)
#define SWZ(off) ((off) ^ (((off) >> 3) & 0x70u))

// ---------------- MMA primitives (baseline PTX; work on compute_103) --------
__device__ __forceinline__ void ldsm4(uint32_t* r, uint32_t addr) {
    asm volatile("ldmatrix.sync.aligned.m8n8.x4.shared.b16 {%0,%1,%2,%3}, [%4];"
        : "=r"(r[0]), "=r"(r[1]), "=r"(r[2]), "=r"(r[3]) : "r"(addr));
}
__device__ __forceinline__ void mma16816(float* c, const uint32_t* a,
                                         uint32_t b0, uint32_t b1) {
    asm volatile(
        "mma.sync.aligned.m16n8k16.row.col.f32.bf16.bf16.f32 "
        "{%0,%1,%2,%3}, {%4,%5,%6,%7}, {%8,%9}, {%0,%1,%2,%3};"
        : "+f"(c[0]), "+f"(c[1]), "+f"(c[2]), "+f"(c[3])
        : "r"(a[0]), "r"(a[1]), "r"(a[2]), "r"(a[3]), "r"(b0), "r"(b1));
}
__device__ __forceinline__ void cpa16(uint32_t dst, const void* src) {
    asm volatile("cp.async.cg.shared.global [%0], [%1], 16;"
                 :: "r"(dst), "l"(src) : "memory");
}
#define CP_COMMIT() asm volatile("cp.async.commit_group;" ::: "memory")
#define CP_WAIT0()  asm volatile("cp.async.wait_group 0;" ::: "memory")
#define CP_WAIT1()  asm volatile("cp.async.wait_group 1;" ::: "memory")

// Tile 128(M) x 64(N), BK=64. Stage: A_hi 16K, A_lo 16K, B_hi 8K, B_lo 8K = 48KB
#define A_HI_OFF 0
#define A_LO_OFF 16384
#define B_HI_OFF 32768
#define B_LO_OFF 40960
#define STAGE_BYTES 49152
#define SMEM_TC     (2*STAGE_BYTES)     // 96KB per CTA -> 2 CTAs/SM
#define HMM_THREADS 256

// Stage one 64-k chunk via cp.async (256 threads: 12 x 16B each)
__device__ __forceinline__ void stage_cp(uint32_t st,
        const uint16_t* __restrict__ Ah, const uint16_t* __restrict__ Al,
        const uint16_t* __restrict__ Bh, const uint16_t* __restrict__ Bl,
        int chunk, int K, int tid) {
    {   // A: 128 rows x 64 k; thread covers 32 k-elems (4 x 16B) for hi and lo
        const int row  = tid >> 1;
        const int half = tid & 1;
        const size_t go = (size_t)row * K + chunk * 64 + half * 32;
        const uint32_t ro = (uint32_t)row * 128 + half * 64;
        #pragma unroll
        for (int j = 0; j < 4; j++) {
            uint32_t sw = SWZ(ro + j * 16);
            cpa16(st + A_HI_OFF + sw, Ah + go + j * 8);
            cpa16(st + A_LO_OFF + sw, Al + go + j * 8);
        }
    }
    {   // B: 64 rows x 64 k; thread covers 16 k-elems (2 x 16B) for hi and lo
        const int row = tid >> 2;
        const int q   = tid & 3;
        const size_t go = (size_t)row * K + chunk * 64 + q * 16;
        const uint32_t ro = (uint32_t)row * 128 + q * 32;
        uint32_t sw0 = SWZ(ro), sw1 = SWZ(ro + 16);
        cpa16(st + B_HI_OFF + sw0, Bh + go);
        cpa16(st + B_HI_OFF + sw1, Bh + go + 8);
        cpa16(st + B_LO_OFF + sw0, Bl + go);
        cpa16(st + B_LO_OFF + sw1, Bl + go + 8);
    }
}

// ---------------- tensor-core GEMM via mma.sync (HMMA) ----------------
// C[M,N] = A[M,K] @ B^T where A=[M][K] hi/lo bf16, B=[N][K] hi/lo bf16.
// MODE 0: +bias  MODE 1: +bias+res  MODE 2: silu(+bias)
// WF32: write f32 C.  WBF: write split-bf16 Oh/Ol.
// blockIdx.z batches independent GEMMs via the *zs element strides.
// 256 threads, 8 warps in 4(M)x2(N) grid, warp tile 32x32, CTA tile 128x64.
// Double-buffered cp.async pipeline; 2 CTAs resident per SM.
// Requires M%128==0, N%64==0, K%64==0, K>=128
template<int MODE, bool WF32, bool WBF>
__global__ __launch_bounds__(HMM_THREADS, 2) void k_hmm(int M, int N, int K,
        const uint16_t* __restrict__ Ah_, const uint16_t* __restrict__ Al_,
        const uint16_t* __restrict__ Bh_, const uint16_t* __restrict__ Bl_,
        float* __restrict__ C, const float* __restrict__ bias,
        const float* __restrict__ res,
        uint16_t* __restrict__ Oh, uint16_t* __restrict__ Ol,
        size_t azs, size_t bzs, size_t czs, size_t ozs, size_t biaszs) {
    extern __shared__ char smem[];
    uint32_t sb = smem_u32(smem);
    const int tid = threadIdx.x;
    const int wid = tid >> 5, lane = tid & 31;
    const int wm = wid & 3, wn = wid >> 2;     // 4 warps M x 2 warps N
    const int m0 = wm * 32, n0 = wn * 32;      // warp tile 32x32

    const int bm = blockIdx.y, bn = blockIdx.x, bz = blockIdx.z;
    const uint16_t* Ah = Ah_ + (size_t)bz * azs + (size_t)bm * 128 * K;
    const uint16_t* Al = Al_ + (size_t)bz * azs + (size_t)bm * 128 * K;
    const uint16_t* Bh = Bh_ + (size_t)bz * bzs + (size_t)bn * 64 * K;
    const uint16_t* Bl = Bl_ + (size_t)bz * bzs + (size_t)bn * 64 * K;
    const float* biasz = bias + (size_t)bz * biaszs;
    const int nchunks = K >> 6;

    float acc[2][4][4];
    #pragma unroll
    for (int a = 0; a < 2; a++)
        #pragma unroll
        for (int b = 0; b < 4; b++)
            #pragma unroll
            for (int c = 0; c < 4; c++) acc[a][b][c] = 0.f;

    // prologue: stage chunks 0 and 1
    stage_cp(sb, Ah, Al, Bh, Bl, 0, K, tid);
    CP_COMMIT();
    stage_cp(sb + STAGE_BYTES, Ah, Al, Bh, Bl, 1, K, tid);
    CP_COMMIT();
    int staged = 2;

    // ldmatrix lane-address components
    const int a_row = m0 + (lane & 15);
    const int a_kof = (lane >> 4) << 3;
    const int b_row = n0 + (lane & 7) + ((lane >> 4) << 3);
    const int b_kof = ((lane >> 3) & 1) << 3;

    for (int i = 0; i < nchunks; i++) {
        if (staged - 1 - i >= 1) { CP_WAIT1(); }
        else                     { CP_WAIT0(); }
        __syncthreads();

        uint32_t st = sb + (i & 1) * STAGE_BYTES;
        uint32_t sA_hi = st + A_HI_OFF;
        uint32_t sA_lo = st + A_LO_OFF;
        uint32_t sB_hi = st + B_HI_OFF;
        uint32_t sB_lo = st + B_LO_OFF;

        #pragma unroll
        for (int ks = 0; ks < 4; ks++) {
            const int k0 = ks << 4;
            uint32_t Bh_f[2][4], Bl_f[2][4], Ah_f[2][4], Al_f[2][4];
            #pragma unroll
            for (int nj = 0; nj < 2; nj++) {
                uint32_t off = SWZ((uint32_t)(b_row + nj * 16) * 128 + (k0 + b_kof) * 2);
                ldsm4(Bh_f[nj], sB_hi + off);
                ldsm4(Bl_f[nj], sB_lo + off);
            }
            #pragma unroll
            for (int mi = 0; mi < 2; mi++) {
                uint32_t off = SWZ((uint32_t)(a_row + mi * 16) * 128 + (k0 + a_kof) * 2);
                ldsm4(Ah_f[mi], sA_hi + off);
                ldsm4(Al_f[mi], sA_lo + off);
            }
            #pragma unroll
            for (int mi = 0; mi < 2; mi++)
                #pragma unroll
                for (int nb = 0; nb < 4; nb++) {
                    const int nj = nb >> 1, s = (nb & 1) << 1;
                    mma16816(acc[mi][nb], Ah_f[mi], Bh_f[nj][s], Bh_f[nj][s + 1]);
                }
            #pragma unroll
            for (int mi = 0; mi < 2; mi++)
                #pragma unroll
                for (int nb = 0; nb < 4; nb++) {
                    const int nj = nb >> 1, s = (nb & 1) << 1;
                    mma16816(acc[mi][nb], Ah_f[mi], Bl_f[nj][s], Bl_f[nj][s + 1]);
                }
            #pragma unroll
            for (int mi = 0; mi < 2; mi++)
                #pragma unroll
                for (int nb = 0; nb < 4; nb++) {
                    const int nj = nb >> 1, s = (nb & 1) << 1;
                    mma16816(acc[mi][nb], Al_f[mi], Bh_f[nj][s], Bh_f[nj][s + 1]);
                }
        }
        __syncthreads();

        // refill the buffer we just finished with chunk i+2
        if (staged < nchunks) {
            stage_cp(sb + (i & 1) * STAGE_BYTES, Ah, Al, Bh, Bl, staged, K, tid);
            CP_COMMIT();
            staged++;
        }
    }

    // ---- epilogue
    const int qr = lane >> 2;          // quad row 0..7
    const int qc = (lane & 3) << 1;    // col pair 0,2,4,6
    #pragma unroll
    for (int mi = 0; mi < 2; mi++) {
        #pragma unroll
        for (int nb = 0; nb < 4; nb++) {
            int col = bn * 64 + n0 + nb * 8 + qc;
            float bz0 = biasz[col], bz1 = biasz[col + 1];
            #pragma unroll
            for (int h = 0; h < 2; h++) {
                int row = bm * 128 + m0 + mi * 16 + qr + h * 8;
                float v0 = acc[mi][nb][h * 2 + 0] + bz0;
                float v1 = acc[mi][nb][h * 2 + 1] + bz1;
                if (MODE == 1) {
                    const float* rp = res + (size_t)row * N + col;
                    v0 += rp[0]; v1 += rp[1];
                }
                if (MODE == 2) { v0 = siluf_(v0); v1 = siluf_(v1); }
                if (WF32) {
                    float* cp = C + (size_t)bz * czs + (size_t)row * N + col;
                    float2 o; o.x = v0; o.y = v1;
                    *(float2*)cp = o;
                }
                if (WBF) {
                    uint16_t h0, l0, h1, l1;
                    split_bf(v0, h0, l0);
                    split_bf(v1, h1, l1);
                    size_t ob = (size_t)bz * ozs + (size_t)row * N + col;
                    *(uint32_t*)(Oh + ob) = (uint32_t)h0 | ((uint32_t)h1 << 16);
                    *(uint32_t*)(Ol + ob) = (uint32_t)l0 | ((uint32_t)l1 << 16);
                }
            }
        }
    }
}

// ---------------- weight convert + transpose: W[K][N] f32 -> T[N][K] hi/lo ---
__global__ __launch_bounds__(256) void k_cvt_wt(const float* __restrict__ W,
        uint16_t* __restrict__ Th, uint16_t* __restrict__ Tl, int K, int N) {
    __shared__ float ts[32][33];
    size_t mo = (size_t)blockIdx.z * K * N;
    const float* Wm = W + mo;
    int n0 = blockIdx.x * 32, k0 = blockIdx.y * 32;
    int tx = threadIdx.x & 31, ty = threadIdx.x >> 5;
    #pragma unroll
    for (int j = 0; j < 32; j += 8)
        ts[ty + j][tx] = Wm[(size_t)(k0 + ty + j) * N + n0 + tx];
    __syncthreads();
    #pragma unroll
    for (int j = 0; j < 32; j += 8) {
        int n = ty + j;
        float v = ts[tx][n];
        uint16_t hh, ll;
        split_bf(v, hh, ll);
        size_t o = mo + (size_t)(n0 + n) * K + k0 + tx;
        Th[o] = hh; Tl[o] = ll;
    }
}

// ---------------- embedding ----------------
__global__ void k_embed(const int* __restrict__ ids,
                        const float* __restrict__ tok,
                        const float* __restrict__ pos,
                        float* __restrict__ out) {
    int idx = blockIdx.x * blockDim.x + threadIdx.x;
    if (idx >= TOK*HD) return;
    int row = idx / HD;
    int h   = idx - row*HD;
    int l   = row & (SEQL-1);
    out[idx] = tok[ids[row]*HD + h] + pos[l*HD + h];
}

// ---------------- layernorm -> split-bf16 (GEMM A operand) ----------------
__global__ __launch_bounds__(256) void k_layernorm_bf(const float* __restrict__ in,
                                                      uint16_t* __restrict__ oh,
                                                      uint16_t* __restrict__ ol,
                                                      const float* __restrict__ w,
                                                      const float* __restrict__ b) {
    int row = blockIdx.x;
    const float* ip = in + (size_t)row * HD;
    int t = threadIdx.x;
    float v0 = ip[t], v1 = ip[t+256], v2 = ip[t+512];
    float s  = v0 + v1 + v2;
    float sq = v0*v0 + v1*v1 + v2*v2;
    #pragma unroll
    for (int o = 16; o > 0; o >>= 1) {
        s  += __shfl_down_sync(0xffffffffu, s, o);
        sq += __shfl_down_sync(0xffffffffu, sq, o);
    }
    __shared__ float sh[16];
    int wid = t >> 5, lane = t & 31;
    if (lane == 0) { sh[wid] = s; sh[8+wid] = sq; }
    __syncthreads();
    if (t == 0) {
        float S = 0.f, Q = 0.f;
        #pragma unroll
        for (int i = 0; i < 8; i++) { S += sh[i]; Q += sh[8+i]; }
        sh[0] = S; sh[8] = Q;
    }
    __syncthreads();
    float mean = sh[0] * (1.0f/HD);
    float var  = sh[8] * (1.0f/HD) - mean*mean;
    float rstd = rsqrtf(var + 1e-5f);
    size_t rb = (size_t)row * HD;
    #pragma unroll
    for (int q = 0; q < 3; q++) {
        int c = t + q * 256;
        float v = (q == 0 ? v0 : (q == 1 ? v1 : v2));
        float ov = (v - mean) * rstd * w[c] + b[c];
        uint16_t hh, ll;
        split_bf(ov, hh, ll);
        oh[rb + c] = hh;
        ol[rb + c] = ll;
    }
}

// ---------------- final layernorm (f32 out) ----------------
__global__ __launch_bounds__(256) void k_layernorm(const float* __restrict__ in,
                                                   float* __restrict__ out,
                                                   const float* __restrict__ w,
                                                   const float* __restrict__ b) {
    int row = blockIdx.x;
    const float* ip = in + (size_t)row * HD;
    int t = threadIdx.x;
    float v0 = ip[t], v1 = ip[t+256], v2 = ip[t+512];
    float s  = v0 + v1 + v2;
    float sq = v0*v0 + v1*v1 + v2*v2;
    #pragma unroll
    for (int o = 16; o > 0; o >>= 1) {
        s  += __shfl_down_sync(0xffffffffu, s, o);
        sq += __shfl_down_sync(0xffffffffu, sq, o);
    }
    __shared__ float sh[16];
    int wid = t >> 5, lane = t & 31;
    if (lane == 0) { sh[wid] = s; sh[8+wid] = sq; }
    __syncthreads();
    if (t == 0) {
        float S = 0.f, Q = 0.f;
        #pragma unroll
        for (int i = 0; i < 8; i++) { S += sh[i]; Q += sh[8+i]; }
        sh[0] = S; sh[8] = Q;
    }
    __syncthreads();
    float mean = sh[0] * (1.0f/HD);
    float var  = sh[8] * (1.0f/HD) - mean*mean;
    float rstd = rsqrtf(var + 1e-5f);
    float* op = out + (size_t)row * HD;
    op[t]     = (v0 - mean)*rstd*w[t]     + b[t];
    op[t+256] = (v1 - mean)*rstd*w[t+256] + b[t+256];
    op[t+512] = (v2 - mean)*rstd*w[t+512] + b[t+512];
}

// ---------------- causal depthwise conv (K=4) + SiLU ----------------
__global__ void k_conv_silu(const float* __restrict__ proj,
                            const float* __restrict__ cw,
                            const float* __restrict__ cb,
                            float* __restrict__ u) {
    int idx = blockIdx.x * blockDim.x + threadIdx.x;
    if (idx >= TOK*ED) return;
    int e   = idx % ED;
    int row = idx / ED;
    int l   = row & (SEQL-1);
    float4 w = ((const float4*)cw)[e];
    const float* xp = proj + (size_t)row*(2*ED) + e;
    float acc = cb[e] + w.w * xp[0];
    if (l >= 1) acc += w.z * xp[-(2*ED)];
    if (l >= 2) acc += w.y * xp[-2*(2*ED)];
    if (l >= 3) acc += w.x * xp[-3*(2*ED)];
    u[idx] = siluf_(acc);
}

// ---------------- dbc = u @ xproj_w  (4096x1536 @ 1536x36) ----------------
__global__ __launch_bounds__(256) void k_gemm_dbc(const float* __restrict__ U,
                                                  const float* __restrict__ W,
                                                  float* __restrict__ out) {
    __shared__ float As[16][64];
    __shared__ float Bs[16][DBCW];
    int r0  = blockIdx.x * 64;
    int tid = threadIdx.x;
    int tr = tid >> 2;
    int tg = tid & 3;
    float acc[9];
    #pragma unroll
    for (int j = 0; j < 9; j++) acc[j] = 0.f;
    for (int k0 = 0; k0 < ED; k0 += 16) {
        float4 av = *(const float4*)(U + (size_t)(r0+tr)*ED + k0 + tg*4);
        As[tg*4+0][tr]=av.x; As[tg*4+1][tr]=av.y; As[tg*4+2][tr]=av.z; As[tg*4+3][tr]=av.w;
        for (int i = tid; i < 16*DBCW; i += 256) {
            int kk = i / DBCW, c = i - kk*DBCW;
            Bs[kk][c] = W[(size_t)(k0+kk)*DBCW + c];
        }
        __syncthreads();
        #pragma unroll
        for (int kk = 0; kk < 16; kk++) {
            float a = As[kk][tr];
            #pragma unroll
            for (int j = 0; j < 9; j++) acc[j] += a * Bs[kk][tg*9+j];
        }
        __syncthreads();
    }
    float* op = out + (size_t)(r0+tr)*DBCW + tg*9;
    #pragma unroll
    for (int j = 0; j < 9; j++) op[j] = acc[j];
}

// ---------------- dt = softplus(dbc[:, :4] @ dt_w + dt_b) ----------------
__global__ void k_dt(const float* __restrict__ dbc,
                     const float* __restrict__ dtw,
                     const float* __restrict__ dtb,
                     float* __restrict__ dt) {
    int idx = blockIdx.x * blockDim.x + threadIdx.x;
    if (idx >= TOK*ED) return;
    int e   = idx % ED;
    int row = idx / ED;
    const float* d = dbc + (size_t)row*DBCW;
    float v = dtb[e];
    v += d[0]*dtw[0*ED+e];
    v += d[1]*dtw[1*ED+e];
    v += d[2]*dtw[2*ED+e];
    v += d[3]*dtw[3*ED+e];
    dt[idx] = softplusf_(v);
}

// ---------------- selective scan v2: cp.async smem staging ------------------
// block = 256 threads (8 warps), 16 channels of one batch; grid = 2*96 = 192
#define SCT 64
__global__ __launch_bounds__(256) void k_scan2(const float* __restrict__ u,
                                               const float* __restrict__ dt,
                                               const float* __restrict__ dbc,
                                               const float* __restrict__ proj,
                                               const float* __restrict__ A_log,
                                               const float* __restrict__ Dv,
                                               uint16_t* __restrict__ yh,
                                               uint16_t* __restrict__ yl) {
    __shared__ float s_bc[2][SCT][32];
    __shared__ float s_u [2][SCT][16];
    __shared__ float s_dt[2][SCT][16];
    __shared__ float s_g [2][SCT][16];

    const int tid  = threadIdx.x;
    const int w    = tid >> 5, lane = tid & 31;
    const int n    = lane & 15, sub = lane >> 4;
    const int b    = blockIdx.x / (ED/16);
    const int grp  = blockIdx.x % (ED/16);
    const int e0   = grp * 16;
    const int el   = w * 2 + sub;
    const int e    = e0 + el;

    const float A2   = -__expf(A_log[e*ND + n]) * 1.44269504088896f;
    const float Dval = Dv[e];
    float h = 0.f;
    const size_t rb = (size_t)b * SEQL;

    auto stage = [&](int buf, int t0) {
        {
            int idx = tid * 2;
            int row = idx >> 3, seg = idx & 7;
            cpa16(smem_u32(&s_bc[buf][row][seg*4]),
                  dbc + (rb + t0 + row)*DBCW + RD + seg*4);
            idx++; row = idx >> 3; seg = idx & 7;
            cpa16(smem_u32(&s_bc[buf][row][seg*4]),
                  dbc + (rb + t0 + row)*DBCW + RD + seg*4);
        }
        {
            int row = tid >> 2, seg = tid & 3;
            cpa16(smem_u32(&s_u [buf][row][seg*4]),
                  u  + (rb + t0 + row)*ED + e0 + seg*4);
            cpa16(smem_u32(&s_dt[buf][row][seg*4]),
                  dt + (rb + t0 + row)*ED + e0 + seg*4);
            cpa16(smem_u32(&s_g [buf][row][seg*4]),
                  proj + (rb + t0 + row)*2*ED + ED + e0 + seg*4);
        }
    };

    stage(0, 0);
    CP_COMMIT();
    const size_t yo_base = rb*ED + e;

    for (int tile = 0; tile < SEQL/SCT; tile++) {
        if (tile + 1 < SEQL/SCT) {
            stage((tile + 1) & 1, (tile + 1) * SCT);
            CP_COMMIT();
            CP_WAIT1();
        } else {
            CP_WAIT0();
        }
        __syncthreads();
        const int buf = tile & 1;
        #pragma unroll 4
        for (int t = 0; t < SCT; t++) {
            float dtv = s_dt[buf][t][el];
            float uv  = s_u [buf][t][el];
            float Bn  = s_bc[buf][t][n];
            float Cn  = s_bc[buf][t][16 + n];
            float dA  = ex2a(dtv * A2);
            h = h*dA + (dtv*uv)*Bn;
            float part = h*Cn;
            part += __shfl_down_sync(0xffffffffu, part, 8, 16);
            part += __shfl_down_sync(0xffffffffu, part, 4, 16);
            part += __shfl_down_sync(0xffffffffu, part, 2, 16);
            part += __shfl_down_sync(0xffffffffu, part, 1, 16);
            if (n == 0) {
                float g = s_g[buf][t][el];
                float v = sigmoidf_(g) * (part + uv*Dval);
                uint16_t hh, ll;
                split_bf(v, hh, ll);
                size_t yo = yo_base + (size_t)(tile*SCT + t)*ED;
                yh[yo] = hh;
                yl[yo] = ll;
            }
        }
        __syncthreads();
    }
}

// ---------------- fractal final: hs += sum(t3) * (0.5/3) ----------------
__global__ void k_frac_add3(float* __restrict__ hs, const float* __restrict__ t3) {
    int idx = blockIdx.x * blockDim.x + threadIdx.x;
    if (idx >= TOK*HD) return;
    hs[idx] += (t3[idx] + t3[idx + TOK*HD] + t3[idx + 2*TOK*HD]) * (0.5f/3.0f);
}

// ---------------- host launcher ----------------
extern "C" void kernel_launch(void* const* d_in, const int* in_sizes, int n_in,
                              void* d_out, int out_size) {
    const int*   ids     = (const int*)  d_in[0];
    const float* tok     = (const float*)d_in[1];
    const float* pos     = (const float*)d_in[2];
    const float* ln_w    = (const float*)d_in[3];
    const float* ln_b    = (const float*)d_in[4];
    const float* in_w    = (const float*)d_in[5];
    const float* in_b    = (const float*)d_in[6];
    const float* conv_w  = (const float*)d_in[7];
    const float* conv_b  = (const float*)d_in[8];
    const float* xproj_w = (const float*)d_in[9];
    const float* dt_w    = (const float*)d_in[10];
    const float* dt_b    = (const float*)d_in[11];
    const float* A_log   = (const float*)d_in[12];
    const float* Dv      = (const float*)d_in[13];
    const float* out_w   = (const float*)d_in[14];
    const float* out_b   = (const float*)d_in[15];
    const float* frac_w  = (const float*)d_in[16];
    const float* frac_b  = (const float*)d_in[17];
    const float* fln_w   = (const float*)d_in[18];
    const float* fln_b   = (const float*)d_in[19];

    float *hs,*proj,*u,*dbc,*dt,*t3;
    uint16_t *wh,*wl,*xh,*xl,*yh,*yl,*hsh,*hsl,*t1h,*t1l,*t2h,*t2l;
    cudaGetSymbolAddress((void**)&hs,   g_hs);
    cudaGetSymbolAddress((void**)&proj, g_proj);
    cudaGetSymbolAddress((void**)&u,    g_u);
    cudaGetSymbolAddress((void**)&dbc,  g_dbc);
    cudaGetSymbolAddress((void**)&dt,   g_dt);
    cudaGetSymbolAddress((void**)&t3,   g_t3);
    cudaGetSymbolAddress((void**)&wh,   g_wh);
    cudaGetSymbolAddress((void**)&wl,   g_wl);
    cudaGetSymbolAddress((void**)&xh,   g_xh);
    cudaGetSymbolAddress((void**)&xl,   g_xl);
    cudaGetSymbolAddress((void**)&yh,   g_yh);
    cudaGetSymbolAddress((void**)&yl,   g_yl);
    cudaGetSymbolAddress((void**)&hsh,  g_hsh);
    cudaGetSymbolAddress((void**)&hsl,  g_hsl);
    cudaGetSymbolAddress((void**)&t1h,  g_t1h);
    cudaGetSymbolAddress((void**)&t1l,  g_t1l);
    cudaGetSymbolAddress((void**)&t2h,  g_t2h);
    cudaGetSymbolAddress((void**)&t2l,  g_t2l);

    cudaFuncSetAttribute(k_hmm<0,true,false>, cudaFuncAttributeMaxDynamicSharedMemorySize, SMEM_TC);
    cudaFuncSetAttribute(k_hmm<1,true,true >, cudaFuncAttributeMaxDynamicSharedMemorySize, SMEM_TC);
    cudaFuncSetAttribute(k_hmm<2,false,true>, cudaFuncAttributeMaxDynamicSharedMemorySize, SMEM_TC);
    cudaFuncSetAttribute(k_hmm<2,true,false>, cudaFuncAttributeMaxDynamicSharedMemorySize, SMEM_TC);

    for (int l = 0; l < NLAYERS; l++) {
        const float* lw   = ln_w   + (size_t)l*HD;
        const float* lb   = ln_b   + (size_t)l*HD;
        const float* iw   = in_w   + (size_t)l*HD*2*ED;
        const float* ib   = in_b   + (size_t)l*2*ED;
        const float* cw   = conv_w + (size_t)l*ED*4;
        const float* cb   = conv_b + (size_t)l*ED;
        const float* xw   = xproj_w+ (size_t)l*ED*DBCW;
        const float* dwp  = dt_w   + (size_t)l*RD*ED;
        const float* dbp  = dt_b   + (size_t)l*ED;
        const float* Al   = A_log  + (size_t)l*ED*ND;
        const float* Dl   = Dv     + (size_t)l*ED;
        const float* ow   = out_w  + (size_t)l*ED*HD;
        const float* ob   = out_b  + (size_t)l*HD;
        const float* fb   = frac_b + (size_t)l*3*HD;

        if (l == 0)
            k_embed<<<(TOK*HD + 255)/256, 256>>>(ids, tok, pos, hs);

        k_cvt_wt<<<dim3(2*ED/32, HD/32, 1), 256>>>(iw, wh+IN_WOFF,  wl+IN_WOFF,  HD, 2*ED);

        k_layernorm_bf<<<TOK, 256>>>(hs, xh, xl, lw, lb);

        // proj = x @ in_w + in_b    [4096 x 3072], K=768  (profile idx 3)
        k_hmm<0,true,false><<<dim3(2*ED/64, TOK/128, 1), HMM_THREADS, SMEM_TC>>>(
            TOK, 2*ED, HD, xh, xl, wh+IN_WOFF, wl+IN_WOFF, proj, ib, nullptr,
            nullptr, nullptr, 0, 0, 0, 0, 0);

        k_cvt_wt<<<dim3(HD/32,  ED/32, 1), 256>>>(ow, wh+OUT_WOFF, wl+OUT_WOFF, ED, HD);
        k_cvt_wt<<<dim3(HD/32,  HD/32, 3), 256>>>(frac_w + (size_t)l*3*HD*HD,
                                                  wh+FRAC_WOFF, wl+FRAC_WOFF, HD, HD);

        k_conv_silu<<<(TOK*ED)/256, 256>>>(proj, cw, cb, u);

        k_gemm_dbc<<<TOK/64, 256>>>(u, xw, dbc);

        k_dt<<<(TOK*ED)/256, 256>>>(dbc, dwp, dbp, dt);

        k_scan2<<<BATCH*(ED/16), 256>>>(u, dt, dbc, proj, Al, Dl, yh, yl);

        // hs = y @ out_w + out_b + hs   [4096 x 768], K=1536; also emit hs hi/lo
        k_hmm<1,true,true><<<dim3(HD/64, TOK/128, 1), HMM_THREADS, SMEM_TC>>>(
            TOK, HD, ED, yh, yl, wh+OUT_WOFF, wl+OUT_WOFF, hs, ob, hs,
            hsh, hsl, 0, 0, 0, 0, 0);

        // fractal tail: 3 independent chains batched over blockIdx.z
        const uint16_t* Wfh = wh + FRAC_WOFF;
        const uint16_t* Wfl = wl + FRAC_WOFF;
        k_hmm<2,false,true><<<dim3(HD/64, TOK/128, 3), HMM_THREADS, SMEM_TC>>>(
            TOK, HD, HD, hsh, hsl, Wfh, Wfl, nullptr, fb, nullptr,
            t1h, t1l, 0, (size_t)HD*HD, 0, (size_t)TOK*HD, HD);
        k_hmm<2,false,true><<<dim3(HD/64, TOK/128, 3), HMM_THREADS, SMEM_TC>>>(
            TOK, HD, HD, t1h, t1l, Wfh, Wfl, nullptr, fb, nullptr,
            t2h, t2l, (size_t)TOK*HD, (size_t)HD*HD, 0, (size_t)TOK*HD, HD);
        k_hmm<2,true,false><<<dim3(HD/64, TOK/128, 3), HMM_THREADS, SMEM_TC>>>(
            TOK, HD, HD, t2h, t2l, Wfh, Wfl, t3, fb, nullptr,
            nullptr, nullptr, (size_t)TOK*HD, (size_t)HD*HD, (size_t)TOK*HD, 0, HD);

        k_frac_add3<<<(TOK*HD)/256, 256>>>(hs, t3);
    }

    k_layernorm<<<TOK, 256>>>(hs, (float*)d_out, fln_w, fln_b);
}

// round 15
// speedup vs baseline: 1.0585x; 1.0585x over previous
#include <cuda_runtime.h>
#include <cuda_bf16.h>
#include <math.h>
#include <stdint.h>

// Problem constants
#define BATCH 2
#define SEQL  2048
#define HD    768
#define ED    1536
#define ND    16
#define RD    4
#define NLAYERS 8
#define TOK   (BATCH*SEQL)     // 4096 tokens
#define DBCW  36               // R + 2N

// weight scratch offsets (elements)
#define IN_WOFF   0
#define OUT_WOFF  (HD*2*ED)
#define FRAC_WOFF (OUT_WOFF + ED*HD)
#define WT_TOTAL  (FRAC_WOFF + 3*HD*HD)

// ---------------- scratch (static device globals; no allocation) -------------
__device__ float g_hs  [TOK*HD];
__device__ float g_proj[TOK*2*ED];
__device__ float g_u   [TOK*ED];
__device__ float g_dbc [TOK*DBCW];
__device__ float g_dt  [TOK*ED];
__device__ float g_t3  [3*TOK*HD];

__device__ __align__(16) uint16_t g_wh [WT_TOTAL];
__device__ __align__(16) uint16_t g_wl [WT_TOTAL];
__device__ __align__(16) uint16_t g_xh [TOK*HD];
__device__ __align__(16) uint16_t g_xl [TOK*HD];
__device__ __align__(16) uint16_t g_yh [TOK*ED];
__device__ __align__(16) uint16_t g_yl [TOK*ED];
__device__ __align__(16) uint16_t g_hsh[TOK*HD];
__device__ __align__(16) uint16_t g_hsl[TOK*HD];
__device__ __align__(16) uint16_t g_t1h[3*TOK*HD];
__device__ __align__(16) uint16_t g_t1l[3*TOK*HD];
__device__ __align__(16) uint16_t g_t2h[3*TOK*HD];
__device__ __align__(16) uint16_t g_t2l[3*TOK*HD];

// ---------------- math helpers ----------------
__device__ __forceinline__ float sigmoidf_(float x) {
    return 1.0f / (1.0f + __expf(-x));
}
__device__ __forceinline__ float siluf_(float x) {
    return x / (1.0f + __expf(-x));
}
__device__ __forceinline__ float softplusf_(float x) {
    if (x > 20.0f) return x;
    return __logf(1.0f + __expf(x));
}
__device__ __forceinline__ float ex2a(float x) {
    float r; asm("ex2.approx.ftz.f32 %0, %1;" : "=f"(r) : "f"(x)); return r;
}
__device__ __forceinline__ void split_bf(float v, uint16_t& h, uint16_t& l) {
    uint32_t b = __float_as_uint(v);
    h = (uint16_t)(b >> 16);
    float hf = __uint_as_float(b & 0xFFFF0000u);
    l = (uint16_t)(__float_as_uint(v - hf) >> 16);
}

__device__ __forceinline__ uint32_t smem_u32(const void* p) {
    uint32_t a;
    asm("{ .reg .u64 t; cvta.to.shared.u64 t, %1; cvt.u32.u64 %0, t; }"
        : "=r"(a) : "l"(p));
    return a;
}

// SW128 swizzle on 128-byte rows (16B granularity)
#define SWZ(off) ((off) ^ (((off) >> 3) & 0x70u))

// ---------------- MMA primitives (baseline PTX; work on compute_103) --------
__device__ __forceinline__ void ldsm4(uint32_t* r, uint32_t addr) {
    asm volatile("ldmatrix.sync.aligned.m8n8.x4.shared.b16 {%0,%1,%2,%3}, [%4];"
        : "=r"(r[0]), "=r"(r[1]), "=r"(r[2]), "=r"(r[3]) : "r"(addr));
}
__device__ __forceinline__ void mma16816(float* c, const uint32_t* a,
                                         uint32_t b0, uint32_t b1) {
    asm volatile(
        "mma.sync.aligned.m16n8k16.row.col.f32.bf16.bf16.f32 "
        "{%0,%1,%2,%3}, {%4,%5,%6,%7}, {%8,%9}, {%0,%1,%2,%3};"
        : "+f"(c[0]), "+f"(c[1]), "+f"(c[2]), "+f"(c[3])
        : "r"(a[0]), "r"(a[1]), "r"(a[2]), "r"(a[3]), "r"(b0), "r"(b1));
}
__device__ __forceinline__ void cpa16(uint32_t dst, const void* src) {
    asm volatile("cp.async.cg.shared.global [%0], [%1], 16;"
                 :: "r"(dst), "l"(src) : "memory");
}
#define CP_COMMIT() asm volatile("cp.async.commit_group;" ::: "memory")
#define CP_WAIT0()  asm volatile("cp.async.wait_group 0;" ::: "memory")
#define CP_WAIT1()  asm volatile("cp.async.wait_group 1;" ::: "memory")
#define CP_WAIT2()  asm volatile("cp.async.wait_group 2;" ::: "memory")

// smem stage layout: A_hi(16K) A_lo(16K) B_hi(16K) B_lo(16K) = 64KB per stage
#define STAGE_BYTES 65536
#define NSTAGE 3
#define SMEM_TC     (NSTAGE*STAGE_BYTES)
#define HMM_THREADS 512

// Stage one 64-k chunk via cp.async (512 threads: 8 x 16B each)
__device__ __forceinline__ void stage_cp(uint32_t st,
        const uint16_t* __restrict__ Ah, const uint16_t* __restrict__ Al,
        const uint16_t* __restrict__ Bh, const uint16_t* __restrict__ Bl,
        int chunk, int K, int tid) {
    const int row = tid >> 2;         // 0..127
    const int q   = tid & 3;          // 16 k-elements each
    const size_t go = (size_t)row * K + chunk * 64 + q * 16;
    const uint32_t ro = (uint32_t)row * 128 + q * 32;
    uint32_t sw0 = SWZ(ro), sw1 = SWZ(ro + 16);
    cpa16(st +         sw0, Ah + go);
    cpa16(st +         sw1, Ah + go + 8);
    cpa16(st + 16384 + sw0, Al + go);
    cpa16(st + 16384 + sw1, Al + go + 8);
    cpa16(st + 32768 + sw0, Bh + go);
    cpa16(st + 32768 + sw1, Bh + go + 8);
    cpa16(st + 49152 + sw0, Bl + go);
    cpa16(st + 49152 + sw1, Bl + go + 8);
}

// load one k-step's fragments into register set S
#define LDFRAGS(ks_, S_) do {                                                     \
    const int k0_ = (ks_) << 4;                                                   \
    _Pragma("unroll")                                                             \
    for (int nj = 0; nj < 2; nj++) {                                              \
        uint32_t off = SWZ((uint32_t)(b_row + nj * 16) * 128 + (k0_ + b_kof) * 2);\
        ldsm4(Bh_f[S_][nj], sB_hi + off);                                         \
        ldsm4(Bl_f[S_][nj], sB_lo + off);                                         \
    }                                                                             \
    _Pragma("unroll")                                                             \
    for (int mi = 0; mi < 2; mi++) {                                              \
        uint32_t off = SWZ((uint32_t)(a_row + mi * 16) * 128 + (k0_ + a_kof) * 2);\
        ldsm4(Ah_f[S_][mi], sA_hi + off);                                         \
        ldsm4(Al_f[S_][mi], sA_lo + off);                                         \
    }                                                                             \
} while (0)

// ---------------- tensor-core GEMM via mma.sync (HMMA) ----------------
// C[M,N] = A[M,K] @ B^T where A=[M][K] hi/lo bf16, B=[N][K] hi/lo bf16.
// MODE 0: +bias  MODE 1: +bias+res  MODE 2: silu(+bias)
// WF32: write f32 C.  WBF: write split-bf16 Oh/Ol.
// blockIdx.z batches independent GEMMs via the *zs element strides.
// 512 threads, 16 warps 4(M)x4(N), warp tile 32x32, CTA tile 128x128.
// 3-stage cp.async pipeline, ONE barrier per chunk, fragment ping-pong.
// Requires M%128==0, N%128==0, K%64==0, K>=256
template<int MODE, bool WF32, bool WBF>
__global__ __launch_bounds__(HMM_THREADS) void k_hmm(int M, int N, int K,
        const uint16_t* __restrict__ Ah_, const uint16_t* __restrict__ Al_,
        const uint16_t* __restrict__ Bh_, const uint16_t* __restrict__ Bl_,
        float* __restrict__ C, const float* __restrict__ bias,
        const float* __restrict__ res,
        uint16_t* __restrict__ Oh, uint16_t* __restrict__ Ol,
        size_t azs, size_t bzs, size_t czs, size_t ozs, size_t biaszs) {
    extern __shared__ char smem[];
    uint32_t sb = smem_u32(smem);
    const int tid = threadIdx.x;
    const int wid = tid >> 5, lane = tid & 31;
    const int wm = wid & 3, wn = wid >> 2;     // 4 warps M x 4 warps N
    const int m0 = wm * 32, n0 = wn * 32;      // warp tile 32x32

    const int bm = blockIdx.y, bn = blockIdx.x, bz = blockIdx.z;
    const uint16_t* Ah = Ah_ + (size_t)bz * azs + (size_t)bm * 128 * K;
    const uint16_t* Al = Al_ + (size_t)bz * azs + (size_t)bm * 128 * K;
    const uint16_t* Bh = Bh_ + (size_t)bz * bzs + (size_t)bn * 128 * K;
    const uint16_t* Bl = Bl_ + (size_t)bz * bzs + (size_t)bn * 128 * K;
    const float* biasz = bias + (size_t)bz * biaszs;
    const int nchunks = K >> 6;

    float acc[2][4][4];
    #pragma unroll
    for (int a = 0; a < 2; a++)
        #pragma unroll
        for (int b = 0; b < 4; b++)
            #pragma unroll
            for (int c = 0; c < 4; c++) acc[a][b][c] = 0.f;

    // prologue: stage chunks 0..2
    stage_cp(sb, Ah, Al, Bh, Bl, 0, K, tid);
    CP_COMMIT();
    stage_cp(sb + STAGE_BYTES, Ah, Al, Bh, Bl, 1, K, tid);
    CP_COMMIT();
    stage_cp(sb + 2*STAGE_BYTES, Ah, Al, Bh, Bl, 2, K, tid);
    CP_COMMIT();
    int staged = 3;

    // ldmatrix lane-address components
    const int a_row = m0 + (lane & 15);
    const int a_kof = (lane >> 4) << 3;
    const int b_row = n0 + (lane & 7) + ((lane >> 4) << 3);
    const int b_kof = ((lane >> 3) & 1) << 3;

    for (int i = 0; i < nchunks; i++) {
        const int pend = staged - i - 1;
        if (pend >= 2)      { CP_WAIT2(); }
        else if (pend == 1) { CP_WAIT1(); }
        else                { CP_WAIT0(); }
        __syncthreads();   // chunk i ready; all warps past reads of buf[(i-1)%3]

        // refill the buffer read in the previous iteration
        if (i >= 1 && staged < nchunks) {
            stage_cp(sb + ((i - 1) % NSTAGE) * STAGE_BYTES, Ah, Al, Bh, Bl,
                     staged, K, tid);
            CP_COMMIT();
            staged++;
        }

        uint32_t st = sb + (i % NSTAGE) * STAGE_BYTES;
        uint32_t sA_hi = st;
        uint32_t sA_lo = st + 16384;
        uint32_t sB_hi = st + 32768;
        uint32_t sB_lo = st + 49152;

        uint32_t Ah_f[2][2][4], Al_f[2][2][4], Bh_f[2][2][4], Bl_f[2][2][4];
        LDFRAGS(0, 0);
        #pragma unroll
        for (int ks = 0; ks < 4; ks++) {
            const int cur = ks & 1, nxt = cur ^ 1;
            if (ks < 3) { LDFRAGS(ks + 1, nxt); }
            #pragma unroll
            for (int mi = 0; mi < 2; mi++)
                #pragma unroll
                for (int nb = 0; nb < 4; nb++) {
                    const int nj = nb >> 1, s = (nb & 1) << 1;
                    mma16816(acc[mi][nb], Ah_f[cur][mi],
                             Bh_f[cur][nj][s], Bh_f[cur][nj][s + 1]);
                }
            #pragma unroll
            for (int mi = 0; mi < 2; mi++)
                #pragma unroll
                for (int nb = 0; nb < 4; nb++) {
                    const int nj = nb >> 1, s = (nb & 1) << 1;
                    mma16816(acc[mi][nb], Ah_f[cur][mi],
                             Bl_f[cur][nj][s], Bl_f[cur][nj][s + 1]);
                }
            #pragma unroll
            for (int mi = 0; mi < 2; mi++)
                #pragma unroll
                for (int nb = 0; nb < 4; nb++) {
                    const int nj = nb >> 1, s = (nb & 1) << 1;
                    mma16816(acc[mi][nb], Al_f[cur][mi],
                             Bh_f[cur][nj][s], Bh_f[cur][nj][s + 1]);
                }
        }
    }

    // ---- epilogue
    const int qr = lane >> 2;          // quad row 0..7
    const int qc = (lane & 3) << 1;    // col pair 0,2,4,6
    #pragma unroll
    for (int mi = 0; mi < 2; mi++) {
        #pragma unroll
        for (int nb = 0; nb < 4; nb++) {
            int col = bn * 128 + n0 + nb * 8 + qc;
            float bz0 = biasz[col], bz1 = biasz[col + 1];
            #pragma unroll
            for (int h = 0; h < 2; h++) {
                int row = bm * 128 + m0 + mi * 16 + qr + h * 8;
                float v0 = acc[mi][nb][h * 2 + 0] + bz0;
                float v1 = acc[mi][nb][h * 2 + 1] + bz1;
                if (MODE == 1) {
                    const float* rp = res + (size_t)row * N + col;
                    v0 += rp[0]; v1 += rp[1];
                }
                if (MODE == 2) { v0 = siluf_(v0); v1 = siluf_(v1); }
                if (WF32) {
                    float* cp = C + (size_t)bz * czs + (size_t)row * N + col;
                    float2 o; o.x = v0; o.y = v1;
                    *(float2*)cp = o;
                }
                if (WBF) {
                    uint16_t h0, l0, h1, l1;
                    split_bf(v0, h0, l0);
                    split_bf(v1, h1, l1);
                    size_t ob = (size_t)bz * ozs + (size_t)row * N + col;
                    *(uint32_t*)(Oh + ob) = (uint32_t)h0 | ((uint32_t)h1 << 16);
                    *(uint32_t*)(Ol + ob) = (uint32_t)l0 | ((uint32_t)l1 << 16);
                }
            }
        }
    }
}

// ---------------- weight convert + transpose: W[K][N] f32 -> T[N][K] hi/lo ---
__global__ __launch_bounds__(256) void k_cvt_wt(const float* __restrict__ W,
        uint16_t* __restrict__ Th, uint16_t* __restrict__ Tl, int K, int N) {
    __shared__ float ts[32][33];
    size_t mo = (size_t)blockIdx.z * K * N;
    const float* Wm = W + mo;
    int n0 = blockIdx.x * 32, k0 = blockIdx.y * 32;
    int tx = threadIdx.x & 31, ty = threadIdx.x >> 5;
    #pragma unroll
    for (int j = 0; j < 32; j += 8)
        ts[ty + j][tx] = Wm[(size_t)(k0 + ty + j) * N + n0 + tx];
    __syncthreads();
    #pragma unroll
    for (int j = 0; j < 32; j += 8) {
        int n = ty + j;
        float v = ts[tx][n];
        uint16_t hh, ll;
        split_bf(v, hh, ll);
        size_t o = mo + (size_t)(n0 + n) * K + k0 + tx;
        Th[o] = hh; Tl[o] = ll;
    }
}

// ---------------- embedding ----------------
__global__ void k_embed(const int* __restrict__ ids,
                        const float* __restrict__ tok,
                        const float* __restrict__ pos,
                        float* __restrict__ out) {
    int idx = blockIdx.x * blockDim.x + threadIdx.x;
    if (idx >= TOK*HD) return;
    int row = idx / HD;
    int h   = idx - row*HD;
    int l   = row & (SEQL-1);
    out[idx] = tok[ids[row]*HD + h] + pos[l*HD + h];
}

// ---------------- layernorm -> split-bf16 (GEMM A operand) ----------------
__global__ __launch_bounds__(256) void k_layernorm_bf(const float* __restrict__ in,
                                                      uint16_t* __restrict__ oh,
                                                      uint16_t* __restrict__ ol,
                                                      const float* __restrict__ w,
                                                      const float* __restrict__ b) {
    int row = blockIdx.x;
    const float* ip = in + (size_t)row * HD;
    int t = threadIdx.x;
    float v0 = ip[t], v1 = ip[t+256], v2 = ip[t+512];
    float s  = v0 + v1 + v2;
    float sq = v0*v0 + v1*v1 + v2*v2;
    #pragma unroll
    for (int o = 16; o > 0; o >>= 1) {
        s  += __shfl_down_sync(0xffffffffu, s, o);
        sq += __shfl_down_sync(0xffffffffu, sq, o);
    }
    __shared__ float sh[16];
    int wid = t >> 5, lane = t & 31;
    if (lane == 0) { sh[wid] = s; sh[8+wid] = sq; }
    __syncthreads();
    if (t == 0) {
        float S = 0.f, Q = 0.f;
        #pragma unroll
        for (int i = 0; i < 8; i++) { S += sh[i]; Q += sh[8+i]; }
        sh[0] = S; sh[8] = Q;
    }
    __syncthreads();
    float mean = sh[0] * (1.0f/HD);
    float var  = sh[8] * (1.0f/HD) - mean*mean;
    float rstd = rsqrtf(var + 1e-5f);
    size_t rb = (size_t)row * HD;
    #pragma unroll
    for (int q = 0; q < 3; q++) {
        int c = t + q * 256;
        float v = (q == 0 ? v0 : (q == 1 ? v1 : v2));
        float ov = (v - mean) * rstd * w[c] + b[c];
        uint16_t hh, ll;
        split_bf(ov, hh, ll);
        oh[rb + c] = hh;
        ol[rb + c] = ll;
    }
}

// ---------------- final layernorm (f32 out) ----------------
__global__ __launch_bounds__(256) void k_layernorm(const float* __restrict__ in,
                                                   float* __restrict__ out,
                                                   const float* __restrict__ w,
                                                   const float* __restrict__ b) {
    int row = blockIdx.x;
    const float* ip = in + (size_t)row * HD;
    int t = threadIdx.x;
    float v0 = ip[t], v1 = ip[t+256], v2 = ip[t+512];
    float s  = v0 + v1 + v2;
    float sq = v0*v0 + v1*v1 + v2*v2;
    #pragma unroll
    for (int o = 16; o > 0; o >>= 1) {
        s  += __shfl_down_sync(0xffffffffu, s, o);
        sq += __shfl_down_sync(0xffffffffu, sq, o);
    }
    __shared__ float sh[16];
    int wid = t >> 5, lane = t & 31;
    if (lane == 0) { sh[wid] = s; sh[8+wid] = sq; }
    __syncthreads();
    if (t == 0) {
        float S = 0.f, Q = 0.f;
        #pragma unroll
        for (int i = 0; i < 8; i++) { S += sh[i]; Q += sh[8+i]; }
        sh[0] = S; sh[8] = Q;
    }
    __syncthreads();
    float mean = sh[0] * (1.0f/HD);
    float var  = sh[8] * (1.0f/HD) - mean*mean;
    float rstd = rsqrtf(var + 1e-5f);
    float* op = out + (size_t)row * HD;
    op[t]     = (v0 - mean)*rstd*w[t]     + b[t];
    op[t+256] = (v1 - mean)*rstd*w[t+256] + b[t+256];
    op[t+512] = (v2 - mean)*rstd*w[t+512] + b[t+512];
}

// ---------------- causal depthwise conv (K=4) + SiLU ----------------
__global__ void k_conv_silu(const float* __restrict__ proj,
                            const float* __restrict__ cw,
                            const float* __restrict__ cb,
                            float* __restrict__ u) {
    int idx = blockIdx.x * blockDim.x + threadIdx.x;
    if (idx >= TOK*ED) return;
    int e   = idx % ED;
    int row = idx / ED;
    int l   = row & (SEQL-1);
    float4 w = ((const float4*)cw)[e];
    const float* xp = proj + (size_t)row*(2*ED) + e;
    float acc = cb[e] + w.w * xp[0];
    if (l >= 1) acc += w.z * xp[-(2*ED)];
    if (l >= 2) acc += w.y * xp[-2*(2*ED)];
    if (l >= 3) acc += w.x * xp[-3*(2*ED)];
    u[idx] = siluf_(acc);
}

// ---------------- dbc = u @ xproj_w  (4096x1536 @ 1536x36) ----------------
__global__ __launch_bounds__(256) void k_gemm_dbc(const float* __restrict__ U,
                                                  const float* __restrict__ W,
                                                  float* __restrict__ out) {
    __shared__ float As[16][64];
    __shared__ float Bs[16][DBCW];
    int r0  = blockIdx.x * 64;
    int tid = threadIdx.x;
    int tr = tid >> 2;
    int tg = tid & 3;
    float acc[9];
    #pragma unroll
    for (int j = 0; j < 9; j++) acc[j] = 0.f;
    for (int k0 = 0; k0 < ED; k0 += 16) {
        float4 av = *(const float4*)(U + (size_t)(r0+tr)*ED + k0 + tg*4);
        As[tg*4+0][tr]=av.x; As[tg*4+1][tr]=av.y; As[tg*4+2][tr]=av.z; As[tg*4+3][tr]=av.w;
        for (int i = tid; i < 16*DBCW; i += 256) {
            int kk = i / DBCW, c = i - kk*DBCW;
            Bs[kk][c] = W[(size_t)(k0+kk)*DBCW + c];
        }
        __syncthreads();
        #pragma unroll
        for (int kk = 0; kk < 16; kk++) {
            float a = As[kk][tr];
            #pragma unroll
            for (int j = 0; j < 9; j++) acc[j] += a * Bs[kk][tg*9+j];
        }
        __syncthreads();
    }
    float* op = out + (size_t)(r0+tr)*DBCW + tg*9;
    #pragma unroll
    for (int j = 0; j < 9; j++) op[j] = acc[j];
}

// ---------------- dt = softplus(dbc[:, :4] @ dt_w + dt_b) ----------------
__global__ void k_dt(const float* __restrict__ dbc,
                     const float* __restrict__ dtw,
                     const float* __restrict__ dtb,
                     float* __restrict__ dt) {
    int idx = blockIdx.x * blockDim.x + threadIdx.x;
    if (idx >= TOK*ED) return;
    int e   = idx % ED;
    int row = idx / ED;
    const float* d = dbc + (size_t)row*DBCW;
    float v = dtb[e];
    v += d[0]*dtw[0*ED+e];
    v += d[1]*dtw[1*ED+e];
    v += d[2]*dtw[2*ED+e];
    v += d[3]*dtw[3*ED+e];
    dt[idx] = softplusf_(v);
}

// ---------------- selective scan v2: cp.async smem staging ------------------
// block = 256 threads (8 warps), 16 channels of one batch; grid = 2*96 = 192
#define SCT 64
__global__ __launch_bounds__(256) void k_scan2(const float* __restrict__ u,
                                               const float* __restrict__ dt,
                                               const float* __restrict__ dbc,
                                               const float* __restrict__ proj,
                                               const float* __restrict__ A_log,
                                               const float* __restrict__ Dv,
                                               uint16_t* __restrict__ yh,
                                               uint16_t* __restrict__ yl) {
    __shared__ float s_bc[2][SCT][32];
    __shared__ float s_u [2][SCT][16];
    __shared__ float s_dt[2][SCT][16];
    __shared__ float s_g [2][SCT][16];

    const int tid  = threadIdx.x;
    const int w    = tid >> 5, lane = tid & 31;
    const int n    = lane & 15, sub = lane >> 4;
    const int b    = blockIdx.x / (ED/16);
    const int grp  = blockIdx.x % (ED/16);
    const int e0   = grp * 16;
    const int el   = w * 2 + sub;
    const int e    = e0 + el;

    const float A2   = -__expf(A_log[e*ND + n]) * 1.44269504088896f;
    const float Dval = Dv[e];
    float h = 0.f;
    const size_t rb = (size_t)b * SEQL;

    auto stage = [&](int buf, int t0) {
        {
            int idx = tid * 2;
            int row = idx >> 3, seg = idx & 7;
            cpa16(smem_u32(&s_bc[buf][row][seg*4]),
                  dbc + (rb + t0 + row)*DBCW + RD + seg*4);
            idx++; row = idx >> 3; seg = idx & 7;
            cpa16(smem_u32(&s_bc[buf][row][seg*4]),
                  dbc + (rb + t0 + row)*DBCW + RD + seg*4);
        }
        {
            int row = tid >> 2, seg = tid & 3;
            cpa16(smem_u32(&s_u [buf][row][seg*4]),
                  u  + (rb + t0 + row)*ED + e0 + seg*4);
            cpa16(smem_u32(&s_dt[buf][row][seg*4]),
                  dt + (rb + t0 + row)*ED + e0 + seg*4);
            cpa16(smem_u32(&s_g [buf][row][seg*4]),
                  proj + (rb + t0 + row)*2*ED + ED + e0 + seg*4);
        }
    };

    stage(0, 0);
    CP_COMMIT();
    const size_t yo_base = rb*ED + e;

    for (int tile = 0; tile < SEQL/SCT; tile++) {
        if (tile + 1 < SEQL/SCT) {
            stage((tile + 1) & 1, (tile + 1) * SCT);
            CP_COMMIT();
            CP_WAIT1();
        } else {
            CP_WAIT0();
        }
        __syncthreads();
        const int buf = tile & 1;
        #pragma unroll 4
        for (int t = 0; t < SCT; t++) {
            float dtv = s_dt[buf][t][el];
            float uv  = s_u [buf][t][el];
            float Bn  = s_bc[buf][t][n];
            float Cn  = s_bc[buf][t][16 + n];
            float dA  = ex2a(dtv * A2);
            h = h*dA + (dtv*uv)*Bn;
            float part = h*Cn;
            part += __shfl_down_sync(0xffffffffu, part, 8, 16);
            part += __shfl_down_sync(0xffffffffu, part, 4, 16);
            part += __shfl_down_sync(0xffffffffu, part, 2, 16);
            part += __shfl_down_sync(0xffffffffu, part, 1, 16);
            if (n == 0) {
                float g = s_g[buf][t][el];
                float v = sigmoidf_(g) * (part + uv*Dval);
                uint16_t hh, ll;
                split_bf(v, hh, ll);
                size_t yo = yo_base + (size_t)(tile*SCT + t)*ED;
                yh[yo] = hh;
                yl[yo] = ll;
            }
        }
        __syncthreads();
    }
}

// ---------------- fractal final: hs += sum(t3) * (0.5/3) ----------------
__global__ void k_frac_add3(float* __restrict__ hs, const float* __restrict__ t3) {
    int idx = blockIdx.x * blockDim.x + threadIdx.x;
    if (idx >= TOK*HD) return;
    hs[idx] += (t3[idx] + t3[idx + TOK*HD] + t3[idx + 2*TOK*HD]) * (0.5f/3.0f);
}

// ---------------- host launcher ----------------
extern "C" void kernel_launch(void* const* d_in, const int* in_sizes, int n_in,
                              void* d_out, int out_size) {
    const int*   ids     = (const int*)  d_in[0];
    const float* tok     = (const float*)d_in[1];
    const float* pos     = (const float*)d_in[2];
    const float* ln_w    = (const float*)d_in[3];
    const float* ln_b    = (const float*)d_in[4];
    const float* in_w    = (const float*)d_in[5];
    const float* in_b    = (const float*)d_in[6];
    const float* conv_w  = (const float*)d_in[7];
    const float* conv_b  = (const float*)d_in[8];
    const float* xproj_w = (const float*)d_in[9];
    const float* dt_w    = (const float*)d_in[10];
    const float* dt_b    = (const float*)d_in[11];
    const float* A_log   = (const float*)d_in[12];
    const float* Dv      = (const float*)d_in[13];
    const float* out_w   = (const float*)d_in[14];
    const float* out_b   = (const float*)d_in[15];
    const float* frac_w  = (const float*)d_in[16];
    const float* frac_b  = (const float*)d_in[17];
    const float* fln_w   = (const float*)d_in[18];
    const float* fln_b   = (const float*)d_in[19];

    float *hs,*proj,*u,*dbc,*dt,*t3;
    uint16_t *wh,*wl,*xh,*xl,*yh,*yl,*hsh,*hsl,*t1h,*t1l,*t2h,*t2l;
    cudaGetSymbolAddress((void**)&hs,   g_hs);
    cudaGetSymbolAddress((void**)&proj, g_proj);
    cudaGetSymbolAddress((void**)&u,    g_u);
    cudaGetSymbolAddress((void**)&dbc,  g_dbc);
    cudaGetSymbolAddress((void**)&dt,   g_dt);
    cudaGetSymbolAddress((void**)&t3,   g_t3);
    cudaGetSymbolAddress((void**)&wh,   g_wh);
    cudaGetSymbolAddress((void**)&wl,   g_wl);
    cudaGetSymbolAddress((void**)&xh,   g_xh);
    cudaGetSymbolAddress((void**)&xl,   g_xl);
    cudaGetSymbolAddress((void**)&yh,   g_yh);
    cudaGetSymbolAddress((void**)&yl,   g_yl);
    cudaGetSymbolAddress((void**)&hsh,  g_hsh);
    cudaGetSymbolAddress((void**)&hsl,  g_hsl);
    cudaGetSymbolAddress((void**)&t1h,  g_t1h);
    cudaGetSymbolAddress((void**)&t1l,  g_t1l);
    cudaGetSymbolAddress((void**)&t2h,  g_t2h);
    cudaGetSymbolAddress((void**)&t2l,  g_t2l);

    cudaFuncSetAttribute(k_hmm<0,true,false>, cudaFuncAttributeMaxDynamicSharedMemorySize, SMEM_TC);
    cudaFuncSetAttribute(k_hmm<1,true,true >, cudaFuncAttributeMaxDynamicSharedMemorySize, SMEM_TC);
    cudaFuncSetAttribute(k_hmm<2,false,true>, cudaFuncAttributeMaxDynamicSharedMemorySize, SMEM_TC);
    cudaFuncSetAttribute(k_hmm<2,true,false>, cudaFuncAttributeMaxDynamicSharedMemorySize, SMEM_TC);

    for (int l = 0; l < NLAYERS; l++) {
        const float* lw   = ln_w   + (size_t)l*HD;
        const float* lb   = ln_b   + (size_t)l*HD;
        const float* iw   = in_w   + (size_t)l*HD*2*ED;
        const float* ib   = in_b   + (size_t)l*2*ED;
        const float* cw   = conv_w + (size_t)l*ED*4;
        const float* cb   = conv_b + (size_t)l*ED;
        const float* xw   = xproj_w+ (size_t)l*ED*DBCW;
        const float* dwp  = dt_w   + (size_t)l*RD*ED;
        const float* dbp  = dt_b   + (size_t)l*ED;
        const float* Al   = A_log  + (size_t)l*ED*ND;
        const float* Dl   = Dv     + (size_t)l*ED;
        const float* ow   = out_w  + (size_t)l*ED*HD;
        const float* ob   = out_b  + (size_t)l*HD;
        const float* fb   = frac_b + (size_t)l*3*HD;

        if (l == 0)
            k_embed<<<(TOK*HD + 255)/256, 256>>>(ids, tok, pos, hs);

        k_cvt_wt<<<dim3(2*ED/32, HD/32, 1), 256>>>(iw, wh+IN_WOFF,  wl+IN_WOFF,  HD, 2*ED);

        k_layernorm_bf<<<TOK, 256>>>(hs, xh, xl, lw, lb);

        // proj = x @ in_w + in_b    [4096 x 3072], K=768  (profile idx 3)
        k_hmm<0,true,false><<<dim3(2*ED/128, TOK/128, 1), HMM_THREADS, SMEM_TC>>>(
            TOK, 2*ED, HD, xh, xl, wh+IN_WOFF, wl+IN_WOFF, proj, ib, nullptr,
            nullptr, nullptr, 0, 0, 0, 0, 0);

        k_cvt_wt<<<dim3(HD/32,  ED/32, 1), 256>>>(ow, wh+OUT_WOFF, wl+OUT_WOFF, ED, HD);
        k_cvt_wt<<<dim3(HD/32,  HD/32, 3), 256>>>(frac_w + (size_t)l*3*HD*HD,
                                                  wh+FRAC_WOFF, wl+FRAC_WOFF, HD, HD);

        k_conv_silu<<<(TOK*ED)/256, 256>>>(proj, cw, cb, u);

        k_gemm_dbc<<<TOK/64, 256>>>(u, xw, dbc);

        k_dt<<<(TOK*ED)/256, 256>>>(dbc, dwp, dbp, dt);

        k_scan2<<<BATCH*(ED/16), 256>>>(u, dt, dbc, proj, Al, Dl, yh, yl);

        // hs = y @ out_w + out_b + hs   [4096 x 768], K=1536; also emit hs hi/lo
        k_hmm<1,true,true><<<dim3(HD/128, TOK/128, 1), HMM_THREADS, SMEM_TC>>>(
            TOK, HD, ED, yh, yl, wh+OUT_WOFF, wl+OUT_WOFF, hs, ob, hs,
            hsh, hsl, 0, 0, 0, 0, 0);

        // fractal tail: 3 independent chains batched over blockIdx.z
        const uint16_t* Wfh = wh + FRAC_WOFF;
        const uint16_t* Wfl = wl + FRAC_WOFF;
        k_hmm<2,false,true><<<dim3(HD/128, TOK/128, 3), HMM_THREADS, SMEM_TC>>>(
            TOK, HD, HD, hsh, hsl, Wfh, Wfl, nullptr, fb, nullptr,
            t1h, t1l, 0, (size_t)HD*HD, 0, (size_t)TOK*HD, HD);
        k_hmm<2,false,true><<<dim3(HD/128, TOK/128, 3), HMM_THREADS, SMEM_TC>>>(
            TOK, HD, HD, t1h, t1l, Wfh, Wfl, nullptr, fb, nullptr,
            t2h, t2l, (size_t)TOK*HD, (size_t)HD*HD, 0, (size_t)TOK*HD, HD);
        k_hmm<2,true,false><<<dim3(HD/128, TOK/128, 3), HMM_THREADS, SMEM_TC>>>(
            TOK, HD, HD, t2h, t2l, Wfh, Wfl, t3, fb, nullptr,
            nullptr, nullptr, (size_t)TOK*HD, (size_t)HD*HD, (size_t)TOK*HD, 0, HD);

        k_frac_add3<<<(TOK*HD)/256, 256>>>(hs, t3);
    }

    k_layernorm<<<TOK, 256>>>(hs, (float*)d_out, fln_w, fln_b);
}

// round 16
// speedup vs baseline: 1.3473x; 1.2729x over previous
#include <cuda_runtime.h>
#include <cuda_bf16.h>
#include <math.h>
#include <stdint.h>

// Problem constants
#define BATCH 2
#define SEQL  2048
#define HD    768
#define ED    1536
#define ND    16
#define RD    4
#define NLAYERS 8
#define TOK   (BATCH*SEQL)     // 4096 tokens
#define DBCW  36               // R + 2N

// weight scratch offsets (elements)
#define IN_WOFF   0
#define OUT_WOFF  (HD*2*ED)
#define FRAC_WOFF (OUT_WOFF + ED*HD)
#define WT_TOTAL  (FRAC_WOFF + 3*HD*HD)

// ---------------- scratch (static device globals; no allocation) -------------
__device__ float g_hs  [TOK*HD];
__device__ float g_proj[TOK*2*ED];
__device__ float g_u   [TOK*ED];
__device__ float g_dbc [TOK*DBCW];
__device__ float g_dt  [TOK*ED];
__device__ float g_t3  [3*TOK*HD];

__device__ __align__(16) uint16_t g_wh [WT_TOTAL];
__device__ __align__(16) uint16_t g_wl [WT_TOTAL];
__device__ __align__(16) uint16_t g_xh [TOK*HD];
__device__ __align__(16) uint16_t g_xl [TOK*HD];
__device__ __align__(16) uint16_t g_yh [TOK*ED];
__device__ __align__(16) uint16_t g_yl [TOK*ED];
__device__ __align__(16) uint16_t g_hsh[TOK*HD];
__device__ __align__(16) uint16_t g_hsl[TOK*HD];
__device__ __align__(16) uint16_t g_t1h[3*TOK*HD];
__device__ __align__(16) uint16_t g_t1l[3*TOK*HD];
__device__ __align__(16) uint16_t g_t2h[3*TOK*HD];
__device__ __align__(16) uint16_t g_t2l[3*TOK*HD];

// ---------------- math helpers ----------------
__device__ __forceinline__ float sigmoidf_(float x) {
    return 1.0f / (1.0f + __expf(-x));
}
__device__ __forceinline__ float siluf_(float x) {
    return x / (1.0f + __expf(-x));
}
__device__ __forceinline__ float softplusf_(float x) {
    if (x > 20.0f) return x;
    return __logf(1.0f + __expf(x));
}
__device__ __forceinline__ float ex2a(float x) {
    float r; asm("ex2.approx.ftz.f32 %0, %1;" : "=f"(r) : "f"(x)); return r;
}
__device__ __forceinline__ void split_bf(float v, uint16_t& h, uint16_t& l) {
    uint32_t b = __float_as_uint(v);
    h = (uint16_t)(b >> 16);
    float hf = __uint_as_float(b & 0xFFFF0000u);
    l = (uint16_t)(__float_as_uint(v - hf) >> 16);
}

__device__ __forceinline__ uint32_t smem_u32(const void* p) {
    uint32_t a;
    asm("{ .reg .u64 t; cvta.to.shared.u64 t, %1; cvt.u32.u64 %0, t; }"
        : "=r"(a) : "l"(p));
    return a;
}

// SW128 swizzle on 128-byte rows (16B granularity)
#define SWZ(off) ((off) ^ (((off) >> 3) & 0x70u))

// ---------------- MMA primitives (baseline PTX; work on compute_103) --------
__device__ __forceinline__ void ldsm4(uint32_t* r, uint32_t addr) {
    asm volatile("ldmatrix.sync.aligned.m8n8.x4.shared.b16 {%0,%1,%2,%3}, [%4];"
        : "=r"(r[0]), "=r"(r[1]), "=r"(r[2]), "=r"(r[3]) : "r"(addr));
}
__device__ __forceinline__ void mma16816(float* c, const uint32_t* a,
                                         uint32_t b0, uint32_t b1) {
    asm volatile(
        "mma.sync.aligned.m16n8k16.row.col.f32.bf16.bf16.f32 "
        "{%0,%1,%2,%3}, {%4,%5,%6,%7}, {%8,%9}, {%0,%1,%2,%3};"
        : "+f"(c[0]), "+f"(c[1]), "+f"(c[2]), "+f"(c[3])
        : "r"(a[0]), "r"(a[1]), "r"(a[2]), "r"(a[3]), "r"(b0), "r"(b1));
}
__device__ __forceinline__ void cpa16(uint32_t dst, const void* src) {
    asm volatile("cp.async.cg.shared.global [%0], [%1], 16;"
                 :: "r"(dst), "l"(src) : "memory");
}
#define CP_COMMIT() asm volatile("cp.async.commit_group;" ::: "memory")
#define CP_WAIT0()  asm volatile("cp.async.wait_group 0;" ::: "memory")
#define CP_WAIT1()  asm volatile("cp.async.wait_group 1;" ::: "memory")
#define CP_WAIT2()  asm volatile("cp.async.wait_group 2;" ::: "memory")

// smem stage layout: A_hi(16K) A_lo(16K) B_hi(16K) B_lo(16K) = 64KB per stage
#define STAGE_BYTES 65536
#define NSTAGE 3
#define SMEM_TC     (NSTAGE*STAGE_BYTES)
#define HMM_THREADS 512

// Stage one 64-k chunk via cp.async (512 threads: 8 x 16B each)
__device__ __forceinline__ void stage_cp(uint32_t st,
        const uint16_t* __restrict__ Ah, const uint16_t* __restrict__ Al,
        const uint16_t* __restrict__ Bh, const uint16_t* __restrict__ Bl,
        int chunk, int K, int tid) {
    const int row = tid >> 2;         // 0..127
    const int q   = tid & 3;          // 16 k-elements each
    const size_t go = (size_t)row * K + chunk * 64 + q * 16;
    const uint32_t ro = (uint32_t)row * 128 + q * 32;
    uint32_t sw0 = SWZ(ro), sw1 = SWZ(ro + 16);
    cpa16(st +         sw0, Ah + go);
    cpa16(st +         sw1, Ah + go + 8);
    cpa16(st + 16384 + sw0, Al + go);
    cpa16(st + 16384 + sw1, Al + go + 8);
    cpa16(st + 32768 + sw0, Bh + go);
    cpa16(st + 32768 + sw1, Bh + go + 8);
    cpa16(st + 49152 + sw0, Bl + go);
    cpa16(st + 49152 + sw1, Bl + go + 8);
}

// ---------------- tensor-core GEMM via mma.sync (HMMA) ----------------
// C[M,N] = A[M,K] @ B^T where A=[M][K] hi/lo bf16, B=[N][K] hi/lo bf16.
// MODE 0: +bias  MODE 1: +bias+res  MODE 2: silu(+bias)
// WF32: write f32 C.  WBF: write split-bf16 Oh/Ol.
// blockIdx.z batches independent GEMMs via the *zs element strides.
// 512 threads, 16 warps 4(M)x4(N), warp tile 32x32, CTA tile 128x128. 3 stages.
template<int MODE, bool WF32, bool WBF>
__global__ __launch_bounds__(HMM_THREADS) void k_hmm(int M, int N, int K,
        const uint16_t* __restrict__ Ah_, const uint16_t* __restrict__ Al_,
        const uint16_t* __restrict__ Bh_, const uint16_t* __restrict__ Bl_,
        float* __restrict__ C, const float* __restrict__ bias,
        const float* __restrict__ res,
        uint16_t* __restrict__ Oh, uint16_t* __restrict__ Ol,
        size_t azs, size_t bzs, size_t czs, size_t ozs, size_t biaszs) {
    extern __shared__ char smem[];
    uint32_t sb = smem_u32(smem);
    const int tid = threadIdx.x;
    const int wid = tid >> 5, lane = tid & 31;
    const int wm = wid & 3, wn = wid >> 2;     // 4 warps M x 4 warps N
    const int m0 = wm * 32, n0 = wn * 32;      // warp tile 32x32

    const int bm = blockIdx.y, bn = blockIdx.x, bz = blockIdx.z;
    const uint16_t* Ah = Ah_ + (size_t)bz * azs + (size_t)bm * 128 * K;
    const uint16_t* Al = Al_ + (size_t)bz * azs + (size_t)bm * 128 * K;
    const uint16_t* Bh = Bh_ + (size_t)bz * bzs + (size_t)bn * 128 * K;
    const uint16_t* Bl = Bl_ + (size_t)bz * bzs + (size_t)bn * 128 * K;
    const float* biasz = bias + (size_t)bz * biaszs;
    const int nchunks = K >> 6;

    float acc[2][4][4];
    #pragma unroll
    for (int a = 0; a < 2; a++)
        #pragma unroll
        for (int b = 0; b < 4; b++)
            #pragma unroll
            for (int c = 0; c < 4; c++) acc[a][b][c] = 0.f;

    // prologue: stage up to 3 chunks
    stage_cp(sb, Ah, Al, Bh, Bl, 0, K, tid);
    CP_COMMIT();
    stage_cp(sb + STAGE_BYTES, Ah, Al, Bh, Bl, 1, K, tid);
    CP_COMMIT();
    stage_cp(sb + 2*STAGE_BYTES, Ah, Al, Bh, Bl, 2, K, tid);
    CP_COMMIT();
    int staged = 3;
    uint32_t bufoff = 0;

    // ldmatrix lane-address components
    const int a_row = m0 + (lane & 15);
    const int a_kof = (lane >> 4) << 3;
    const int b_row = n0 + (lane & 7) + ((lane >> 4) << 3);
    const int b_kof = ((lane >> 3) & 1) << 3;

    for (int i = 0; i < nchunks; i++) {
        const int pend = staged - 1 - i;
        if (pend >= 2)      { CP_WAIT2(); }
        else if (pend == 1) { CP_WAIT1(); }
        else                { CP_WAIT0(); }
        __syncthreads();

        uint32_t sA_hi = sb + bufoff;
        uint32_t sA_lo = sA_hi + 16384;
        uint32_t sB_hi = sA_hi + 32768;
        uint32_t sB_lo = sA_hi + 49152;

        #pragma unroll
        for (int ks = 0; ks < 4; ks++) {
            const int k0 = ks << 4;
            uint32_t Bh_f[2][4], Bl_f[2][4], Ah_f[2][4], Al_f[2][4];
            #pragma unroll
            for (int nj = 0; nj < 2; nj++) {
                uint32_t off = SWZ((uint32_t)(b_row + nj * 16) * 128 + (k0 + b_kof) * 2);
                ldsm4(Bh_f[nj], sB_hi + off);
                ldsm4(Bl_f[nj], sB_lo + off);
            }
            #pragma unroll
            for (int mi = 0; mi < 2; mi++) {
                uint32_t off = SWZ((uint32_t)(a_row + mi * 16) * 128 + (k0 + a_kof) * 2);
                ldsm4(Ah_f[mi], sA_hi + off);
                ldsm4(Al_f[mi], sA_lo + off);
            }
            #pragma unroll
            for (int mi = 0; mi < 2; mi++)
                #pragma unroll
                for (int nb = 0; nb < 4; nb++) {
                    const int nj = nb >> 1, s = (nb & 1) << 1;
                    mma16816(acc[mi][nb], Ah_f[mi], Bh_f[nj][s], Bh_f[nj][s + 1]);
                }
            #pragma unroll
            for (int mi = 0; mi < 2; mi++)
                #pragma unroll
                for (int nb = 0; nb < 4; nb++) {
                    const int nj = nb >> 1, s = (nb & 1) << 1;
                    mma16816(acc[mi][nb], Ah_f[mi], Bl_f[nj][s], Bl_f[nj][s + 1]);
                }
            #pragma unroll
            for (int mi = 0; mi < 2; mi++)
                #pragma unroll
                for (int nb = 0; nb < 4; nb++) {
                    const int nj = nb >> 1, s = (nb & 1) << 1;
                    mma16816(acc[mi][nb], Al_f[mi], Bh_f[nj][s], Bh_f[nj][s + 1]);
                }
        }
        __syncthreads();

        // refill the buffer we just finished with chunk i+3
        if (staged < nchunks) {
            stage_cp(sb + bufoff, Ah, Al, Bh, Bl, staged, K, tid);
            CP_COMMIT();
            staged++;
        }
        bufoff += STAGE_BYTES;
        if (bufoff == NSTAGE * STAGE_BYTES) bufoff = 0;
    }

    // ---- epilogue
    const int qr = lane >> 2;          // quad row 0..7
    const int qc = (lane & 3) << 1;    // col pair 0,2,4,6
    #pragma unroll
    for (int mi = 0; mi < 2; mi++) {
        #pragma unroll
        for (int nb = 0; nb < 4; nb++) {
            int col = bn * 128 + n0 + nb * 8 + qc;
            float bz0 = biasz[col], bz1 = biasz[col + 1];
            #pragma unroll
            for (int h = 0; h < 2; h++) {
                int row = bm * 128 + m0 + mi * 16 + qr + h * 8;
                float v0 = acc[mi][nb][h * 2 + 0] + bz0;
                float v1 = acc[mi][nb][h * 2 + 1] + bz1;
                if (MODE == 1) {
                    const float* rp = res + (size_t)row * N + col;
                    v0 += rp[0]; v1 += rp[1];
                }
                if (MODE == 2) { v0 = siluf_(v0); v1 = siluf_(v1); }
                if (WF32) {
                    float* cp = C + (size_t)bz * czs + (size_t)row * N + col;
                    float2 o; o.x = v0; o.y = v1;
                    *(float2*)cp = o;
                }
                if (WBF) {
                    uint16_t h0, l0, h1, l1;
                    split_bf(v0, h0, l0);
                    split_bf(v1, h1, l1);
                    size_t ob = (size_t)bz * ozs + (size_t)row * N + col;
                    *(uint32_t*)(Oh + ob) = (uint32_t)h0 | ((uint32_t)h1 << 16);
                    *(uint32_t*)(Ol + ob) = (uint32_t)l0 | ((uint32_t)l1 << 16);
                }
            }
        }
    }
}

// ---------------- weight convert + transpose: W[K][N] f32 -> T[N][K] hi/lo ---
__global__ __launch_bounds__(256) void k_cvt_wt(const float* __restrict__ W,
        uint16_t* __restrict__ Th, uint16_t* __restrict__ Tl, int K, int N) {
    __shared__ float ts[32][33];
    size_t mo = (size_t)blockIdx.z * K * N;
    const float* Wm = W + mo;
    int n0 = blockIdx.x * 32, k0 = blockIdx.y * 32;
    int tx = threadIdx.x & 31, ty = threadIdx.x >> 5;
    #pragma unroll
    for (int j = 0; j < 32; j += 8)
        ts[ty + j][tx] = Wm[(size_t)(k0 + ty + j) * N + n0 + tx];
    __syncthreads();
    #pragma unroll
    for (int j = 0; j < 32; j += 8) {
        int n = ty + j;
        float v = ts[tx][n];
        uint16_t hh, ll;
        split_bf(v, hh, ll);
        size_t o = mo + (size_t)(n0 + n) * K + k0 + tx;
        Th[o] = hh; Tl[o] = ll;
    }
}

// ---------------- embedding ----------------
__global__ void k_embed(const int* __restrict__ ids,
                        const float* __restrict__ tok,
                        const float* __restrict__ pos,
                        float* __restrict__ out) {
    int idx = blockIdx.x * blockDim.x + threadIdx.x;
    if (idx >= TOK*HD) return;
    int row = idx / HD;
    int h   = idx - row*HD;
    int l   = row & (SEQL-1);
    out[idx] = tok[ids[row]*HD + h] + pos[l*HD + h];
}

// ---------------- layernorm -> split-bf16 (GEMM A operand) ----------------
__global__ __launch_bounds__(256) void k_layernorm_bf(const float* __restrict__ in,
                                                      uint16_t* __restrict__ oh,
                                                      uint16_t* __restrict__ ol,
                                                      const float* __restrict__ w,
                                                      const float* __restrict__ b) {
    int row = blockIdx.x;
    const float* ip = in + (size_t)row * HD;
    int t = threadIdx.x;
    float v0 = ip[t], v1 = ip[t+256], v2 = ip[t+512];
    float s  = v0 + v1 + v2;
    float sq = v0*v0 + v1*v1 + v2*v2;
    #pragma unroll
    for (int o = 16; o > 0; o >>= 1) {
        s  += __shfl_down_sync(0xffffffffu, s, o);
        sq += __shfl_down_sync(0xffffffffu, sq, o);
    }
    __shared__ float sh[16];
    int wid = t >> 5, lane = t & 31;
    if (lane == 0) { sh[wid] = s; sh[8+wid] = sq; }
    __syncthreads();
    if (t == 0) {
        float S = 0.f, Q = 0.f;
        #pragma unroll
        for (int i = 0; i < 8; i++) { S += sh[i]; Q += sh[8+i]; }
        sh[0] = S; sh[8] = Q;
    }
    __syncthreads();
    float mean = sh[0] * (1.0f/HD);
    float var  = sh[8] * (1.0f/HD) - mean*mean;
    float rstd = rsqrtf(var + 1e-5f);
    size_t rb = (size_t)row * HD;
    #pragma unroll
    for (int q = 0; q < 3; q++) {
        int c = t + q * 256;
        float v = (q == 0 ? v0 : (q == 1 ? v1 : v2));
        float ov = (v - mean) * rstd * w[c] + b[c];
        uint16_t hh, ll;
        split_bf(ov, hh, ll);
        oh[rb + c] = hh;
        ol[rb + c] = ll;
    }
}

// ---------------- final layernorm (f32 out) ----------------
__global__ __launch_bounds__(256) void k_layernorm(const float* __restrict__ in,
                                                   float* __restrict__ out,
                                                   const float* __restrict__ w,
                                                   const float* __restrict__ b) {
    int row = blockIdx.x;
    const float* ip = in + (size_t)row * HD;
    int t = threadIdx.x;
    float v0 = ip[t], v1 = ip[t+256], v2 = ip[t+512];
    float s  = v0 + v1 + v2;
    float sq = v0*v0 + v1*v1 + v2*v2;
    #pragma unroll
    for (int o = 16; o > 0; o >>= 1) {
        s  += __shfl_down_sync(0xffffffffu, s, o);
        sq += __shfl_down_sync(0xffffffffu, sq, o);
    }
    __shared__ float sh[16];
    int wid = t >> 5, lane = t & 31;
    if (lane == 0) { sh[wid] = s; sh[8+wid] = sq; }
    __syncthreads();
    if (t == 0) {
        float S = 0.f, Q = 0.f;
        #pragma unroll
        for (int i = 0; i < 8; i++) { S += sh[i]; Q += sh[8+i]; }
        sh[0] = S; sh[8] = Q;
    }
    __syncthreads();
    float mean = sh[0] * (1.0f/HD);
    float var  = sh[8] * (1.0f/HD) - mean*mean;
    float rstd = rsqrtf(var + 1e-5f);
    float* op = out + (size_t)row * HD;
    op[t]     = (v0 - mean)*rstd*w[t]     + b[t];
    op[t+256] = (v1 - mean)*rstd*w[t+256] + b[t+256];
    op[t+512] = (v2 - mean)*rstd*w[t+512] + b[t+512];
}

// ---------------- causal depthwise conv (K=4) + SiLU ----------------
__global__ void k_conv_silu(const float* __restrict__ proj,
                            const float* __restrict__ cw,
                            const float* __restrict__ cb,
                            float* __restrict__ u) {
    int idx = blockIdx.x * blockDim.x + threadIdx.x;
    if (idx >= TOK*ED) return;
    int e   = idx % ED;
    int row = idx / ED;
    int l   = row & (SEQL-1);
    float4 w = ((const float4*)cw)[e];
    const float* xp = proj + (size_t)row*(2*ED) + e;
    float acc = cb[e] + w.w * xp[0];
    if (l >= 1) acc += w.z * xp[-(2*ED)];
    if (l >= 2) acc += w.y * xp[-2*(2*ED)];
    if (l >= 3) acc += w.x * xp[-3*(2*ED)];
    u[idx] = siluf_(acc);
}

// ---------------- dbc = u @ xproj_w  (4096x1536 @ 1536x36) ----------------
__global__ __launch_bounds__(256) void k_gemm_dbc(const float* __restrict__ U,
                                                  const float* __restrict__ W,
                                                  float* __restrict__ out) {
    __shared__ float As[16][64];
    __shared__ float Bs[16][DBCW];
    int r0  = blockIdx.x * 64;
    int tid = threadIdx.x;
    int tr = tid >> 2;
    int tg = tid & 3;
    float acc[9];
    #pragma unroll
    for (int j = 0; j < 9; j++) acc[j] = 0.f;
    for (int k0 = 0; k0 < ED; k0 += 16) {
        float4 av = *(const float4*)(U + (size_t)(r0+tr)*ED + k0 + tg*4);
        As[tg*4+0][tr]=av.x; As[tg*4+1][tr]=av.y; As[tg*4+2][tr]=av.z; As[tg*4+3][tr]=av.w;
        for (int i = tid; i < 16*DBCW; i += 256) {
            int kk = i / DBCW, c = i - kk*DBCW;
            Bs[kk][c] = W[(size_t)(k0+kk)*DBCW + c];
        }
        __syncthreads();
        #pragma unroll
        for (int kk = 0; kk < 16; kk++) {
            float a = As[kk][tr];
            #pragma unroll
            for (int j = 0; j < 9; j++) acc[j] += a * Bs[kk][tg*9+j];
        }
        __syncthreads();
    }
    float* op = out + (size_t)(r0+tr)*DBCW + tg*9;
    #pragma unroll
    for (int j = 0; j < 9; j++) op[j] = acc[j];
}

// ---------------- dt = softplus(dbc[:, :4] @ dt_w + dt_b) ----------------
__global__ void k_dt(const float* __restrict__ dbc,
                     const float* __restrict__ dtw,
                     const float* __restrict__ dtb,
                     float* __restrict__ dt) {
    int idx = blockIdx.x * blockDim.x + threadIdx.x;
    if (idx >= TOK*ED) return;
    int e   = idx % ED;
    int row = idx / ED;
    const float* d = dbc + (size_t)row*DBCW;
    float v = dtb[e];
    v += d[0]*dtw[0*ED+e];
    v += d[1]*dtw[1*ED+e];
    v += d[2]*dtw[2*ED+e];
    v += d[3]*dtw[3*ED+e];
    dt[idx] = softplusf_(v);
}

// ---------------- selective scan v3: no shuffles in serial loop -------------
// block = 256 threads (8 warps), 16 channels of one batch; grid = 192.
// Serial loop writes h*C contributions to smem; every 16 steps a parallel
// pass reduces 16 states -> y (sigmoid(gate)*(sum + u*D)) and stores bf16.
// dynamic smem (floats):
//   f_bc [2][64][32]   @     0 (4096)
//   f_u  [2][64][16]   @  4096 (2048)
//   f_dt [2][64][16]   @  6144 (2048)
//   f_g  [2][64][16]   @  8192 (2048)
//   f_hc [16][16*20]   @ 10240 (5120)   row stride 20 floats (pad vs conflicts)
#define SCT 64
#define SC_SMEM (15360*4)
__global__ __launch_bounds__(256) void k_scan3(const float* __restrict__ u,
                                               const float* __restrict__ dt,
                                               const float* __restrict__ dbc,
                                               const float* __restrict__ proj,
                                               const float* __restrict__ A_log,
                                               const float* __restrict__ Dv,
                                               uint16_t* __restrict__ yh,
                                               uint16_t* __restrict__ yl) {
    extern __shared__ float sm[];
    uint32_t smb = smem_u32(sm);
    const int tid  = threadIdx.x;
    const int w    = tid >> 5, lane = tid & 31;
    const int n    = lane & 15, sub = lane >> 4;
    const int b    = blockIdx.x / (ED/16);
    const int grp  = blockIdx.x % (ED/16);
    const int e0   = grp * 16;
    const int el   = w * 2 + sub;
    const int e    = e0 + el;

    const float A2 = -__expf(A_log[e*ND + n]) * 1.44269504088896f;
    float h = 0.f;
    const size_t rb = (size_t)b * SEQL;

    const int elr = tid & 15;           // reduction channel
    const int tlr = tid >> 4;           // reduction local step 0..15
    const float Dr = Dv[e0 + elr];

    float* f_u  = sm + 4096;
    float* f_dt = sm + 6144;
    float* f_g  = sm + 8192;
    float* f_hc = sm + 10240;

    auto stage = [&](int buf, int t0) {
        {   // dbc B|C rows: 128B each (2 cps/thread)
            int idx = tid * 2;
            int row = idx >> 3, seg = idx & 7;
            cpa16(smb + (uint32_t)(buf*2048 + row*32 + seg*4)*4,
                  dbc + (rb + t0 + row)*DBCW + RD + seg*4);
            idx++; row = idx >> 3; seg = idx & 7;
            cpa16(smb + (uint32_t)(buf*2048 + row*32 + seg*4)*4,
                  dbc + (rb + t0 + row)*DBCW + RD + seg*4);
        }
        {   // u/dt/gate rows: 64B each (1 cp each)
            int row = tid >> 2, seg = tid & 3;
            cpa16(smb + (uint32_t)(4096 + buf*1024 + row*16 + seg*4)*4,
                  u  + (rb + t0 + row)*ED + e0 + seg*4);
            cpa16(smb + (uint32_t)(6144 + buf*1024 + row*16 + seg*4)*4,
                  dt + (rb + t0 + row)*ED + e0 + seg*4);
            cpa16(smb + (uint32_t)(8192 + buf*1024 + row*16 + seg*4)*4,
                  proj + (rb + t0 + row)*2*ED + ED + e0 + seg*4);
        }
    };

    stage(0, 0);
    CP_COMMIT();

    for (int tile = 0; tile < SEQL/SCT; tile++) {
        if (tile + 1 < SEQL/SCT) {
            stage((tile + 1) & 1, (tile + 1) * SCT);
            CP_COMMIT();
            CP_WAIT1();
        } else {
            CP_WAIT0();
        }
        __syncthreads();
        const int buf = tile & 1;

        #pragma unroll
        for (int g4 = 0; g4 < 4; g4++) {
            // serial scan for 16 steps, contributions -> smem
            #pragma unroll 4
            for (int tt = 0; tt < 16; tt++) {
                const int t = g4 * 16 + tt;
                float dtv = f_dt[buf*1024 + t*16 + el];
                float uv  = f_u [buf*1024 + t*16 + el];
                float Bn  = sm  [buf*2048 + t*32 + n];
                float Cn  = sm  [buf*2048 + t*32 + 16 + n];
                float dA  = ex2a(dtv * A2);
                h = h*dA + (dtv*uv)*Bn;
                f_hc[tt*320 + el*20 + n] = h * Cn;
            }
            __syncthreads();
            // parallel reduce: one output per thread
            {
                const int t = g4 * 16 + tlr;
                const float4* hp = (const float4*)&f_hc[tlr*320 + elr*20];
                float4 a0 = hp[0], a1 = hp[1], a2 = hp[2], a3 = hp[3];
                float s = (((a0.x + a0.y) + (a0.z + a0.w)) +
                           ((a1.x + a1.y) + (a1.z + a1.w))) +
                          (((a2.x + a2.y) + (a2.z + a2.w)) +
                           ((a3.x + a3.y) + (a3.z + a3.w)));
                float uv = f_u[buf*1024 + t*16 + elr];
                float g  = f_g[buf*1024 + t*16 + elr];
                float v  = sigmoidf_(g) * (s + uv * Dr);
                uint16_t hh, ll;
                split_bf(v, hh, ll);
                size_t yo = (rb + tile*SCT + t)*ED + e0 + elr;
                yh[yo] = hh;
                yl[yo] = ll;
            }
            __syncthreads();
        }
    }
}

// ---------------- fractal final: hs += sum(t3) * (0.5/3) ----------------
__global__ void k_frac_add3(float* __restrict__ hs, const float* __restrict__ t3) {
    int idx = blockIdx.x * blockDim.x + threadIdx.x;
    if (idx >= TOK*HD) return;
    hs[idx] += (t3[idx] + t3[idx + TOK*HD] + t3[idx + 2*TOK*HD]) * (0.5f/3.0f);
}

// ---------------- host launcher ----------------
extern "C" void kernel_launch(void* const* d_in, const int* in_sizes, int n_in,
                              void* d_out, int out_size) {
    const int*   ids     = (const int*)  d_in[0];
    const float* tok     = (const float*)d_in[1];
    const float* pos     = (const float*)d_in[2];
    const float* ln_w    = (const float*)d_in[3];
    const float* ln_b    = (const float*)d_in[4];
    const float* in_w    = (const float*)d_in[5];
    const float* in_b    = (const float*)d_in[6];
    const float* conv_w  = (const float*)d_in[7];
    const float* conv_b  = (const float*)d_in[8];
    const float* xproj_w = (const float*)d_in[9];
    const float* dt_w    = (const float*)d_in[10];
    const float* dt_b    = (const float*)d_in[11];
    const float* A_log   = (const float*)d_in[12];
    const float* Dv      = (const float*)d_in[13];
    const float* out_w   = (const float*)d_in[14];
    const float* out_b   = (const float*)d_in[15];
    const float* frac_w  = (const float*)d_in[16];
    const float* frac_b  = (const float*)d_in[17];
    const float* fln_w   = (const float*)d_in[18];
    const float* fln_b   = (const float*)d_in[19];

    float *hs,*proj,*u,*dbc,*dt,*t3;
    uint16_t *wh,*wl,*xh,*xl,*yh,*yl,*hsh,*hsl,*t1h,*t1l,*t2h,*t2l;
    cudaGetSymbolAddress((void**)&hs,   g_hs);
    cudaGetSymbolAddress((void**)&proj, g_proj);
    cudaGetSymbolAddress((void**)&u,    g_u);
    cudaGetSymbolAddress((void**)&dbc,  g_dbc);
    cudaGetSymbolAddress((void**)&dt,   g_dt);
    cudaGetSymbolAddress((void**)&t3,   g_t3);
    cudaGetSymbolAddress((void**)&wh,   g_wh);
    cudaGetSymbolAddress((void**)&wl,   g_wl);
    cudaGetSymbolAddress((void**)&xh,   g_xh);
    cudaGetSymbolAddress((void**)&xl,   g_xl);
    cudaGetSymbolAddress((void**)&yh,   g_yh);
    cudaGetSymbolAddress((void**)&yl,   g_yl);
    cudaGetSymbolAddress((void**)&hsh,  g_hsh);
    cudaGetSymbolAddress((void**)&hsl,  g_hsl);
    cudaGetSymbolAddress((void**)&t1h,  g_t1h);
    cudaGetSymbolAddress((void**)&t1l,  g_t1l);
    cudaGetSymbolAddress((void**)&t2h,  g_t2h);
    cudaGetSymbolAddress((void**)&t2l,  g_t2l);

    cudaFuncSetAttribute(k_hmm<0,true,false>, cudaFuncAttributeMaxDynamicSharedMemorySize, SMEM_TC);
    cudaFuncSetAttribute(k_hmm<1,true,true >, cudaFuncAttributeMaxDynamicSharedMemorySize, SMEM_TC);
    cudaFuncSetAttribute(k_hmm<2,false,true>, cudaFuncAttributeMaxDynamicSharedMemorySize, SMEM_TC);
    cudaFuncSetAttribute(k_hmm<2,true,false>, cudaFuncAttributeMaxDynamicSharedMemorySize, SMEM_TC);
    cudaFuncSetAttribute(k_scan3, cudaFuncAttributeMaxDynamicSharedMemorySize, SC_SMEM);

    for (int l = 0; l < NLAYERS; l++) {
        const float* lw   = ln_w   + (size_t)l*HD;
        const float* lb   = ln_b   + (size_t)l*HD;
        const float* iw   = in_w   + (size_t)l*HD*2*ED;
        const float* ib   = in_b   + (size_t)l*2*ED;
        const float* cw   = conv_w + (size_t)l*ED*4;
        const float* cb   = conv_b + (size_t)l*ED;
        const float* xw   = xproj_w+ (size_t)l*ED*DBCW;
        const float* dwp  = dt_w   + (size_t)l*RD*ED;
        const float* dbp  = dt_b   + (size_t)l*ED;
        const float* Al   = A_log  + (size_t)l*ED*ND;
        const float* Dl   = Dv     + (size_t)l*ED;
        const float* ow   = out_w  + (size_t)l*ED*HD;
        const float* ob   = out_b  + (size_t)l*HD;
        const float* fb   = frac_b + (size_t)l*3*HD;

        if (l == 0)
            k_embed<<<(TOK*HD + 255)/256, 256>>>(ids, tok, pos, hs);

        k_cvt_wt<<<dim3(2*ED/32, HD/32, 1), 256>>>(iw, wh+IN_WOFF,  wl+IN_WOFF,  HD, 2*ED);

        k_layernorm_bf<<<TOK, 256>>>(hs, xh, xl, lw, lb);

        // proj = x @ in_w + in_b    [4096 x 3072], K=768  (profile idx 3)
        k_hmm<0,true,false><<<dim3(2*ED/128, TOK/128, 1), HMM_THREADS, SMEM_TC>>>(
            TOK, 2*ED, HD, xh, xl, wh+IN_WOFF, wl+IN_WOFF, proj, ib, nullptr,
            nullptr, nullptr, 0, 0, 0, 0, 0);

        k_cvt_wt<<<dim3(HD/32,  ED/32, 1), 256>>>(ow, wh+OUT_WOFF, wl+OUT_WOFF, ED, HD);
        k_cvt_wt<<<dim3(HD/32,  HD/32, 3), 256>>>(frac_w + (size_t)l*3*HD*HD,
                                                  wh+FRAC_WOFF, wl+FRAC_WOFF, HD, HD);

        k_conv_silu<<<(TOK*ED)/256, 256>>>(proj, cw, cb, u);

        k_gemm_dbc<<<TOK/64, 256>>>(u, xw, dbc);

        k_dt<<<(TOK*ED)/256, 256>>>(dbc, dwp, dbp, dt);

        k_scan3<<<BATCH*(ED/16), 256, SC_SMEM>>>(u, dt, dbc, proj, Al, Dl, yh, yl);

        // hs = y @ out_w + out_b + hs   [4096 x 768], K=1536; also emit hs hi/lo
        k_hmm<1,true,true><<<dim3(HD/128, TOK/128, 1), HMM_THREADS, SMEM_TC>>>(
            TOK, HD, ED, yh, yl, wh+OUT_WOFF, wl+OUT_WOFF, hs, ob, hs,
            hsh, hsl, 0, 0, 0, 0, 0);

        // fractal tail: 3 independent chains batched over blockIdx.z
        const uint16_t* Wfh = wh + FRAC_WOFF;
        const uint16_t* Wfl = wl + FRAC_WOFF;
        k_hmm<2,false,true><<<dim3(HD/128, TOK/128, 3), HMM_THREADS, SMEM_TC>>>(
            TOK, HD, HD, hsh, hsl, Wfh, Wfl, nullptr, fb, nullptr,
            t1h, t1l, 0, (size_t)HD*HD, 0, (size_t)TOK*HD, HD);
        k_hmm<2,false,true><<<dim3(HD/128, TOK/128, 3), HMM_THREADS, SMEM_TC>>>(
            TOK, HD, HD, t1h, t1l, Wfh, Wfl, nullptr, fb, nullptr,
            t2h, t2l, (size_t)TOK*HD, (size_t)HD*HD, 0, (size_t)TOK*HD, HD);
        k_hmm<2,true,false><<<dim3(HD/128, TOK/128, 3), HMM_THREADS, SMEM_TC>>>(
            TOK, HD, HD, t2h, t2l, Wfh, Wfl, t3, fb, nullptr,
            nullptr, nullptr, (size_t)TOK*HD, (size_t)HD*HD, (size_t)TOK*HD, 0, HD);

        k_frac_add3<<<(TOK*HD)/256, 256>>>(hs, t3);
    }

    k_layernorm<<<TOK, 256>>>(hs, (float*)d_out, fln_w, fln_b);
}